// round 4
// baseline (speedup 1.0000x reference)
#include <cuda_runtime.h>
#include <cuda_bf16.h>
#include <cstdint>
#include <math.h>

#define B_  4
#define T_  2048
#define D_  1024
#define NH_ 16
#define HD_ 64
#define BT_ (B_*T_)
#define KP  3072          // packed contraction length = 3*D_

// ------------------------- scratch -------------------------
__device__ __align__(128) __nv_bfloat16 g_xp[(size_t)BT_*KP];     // x packed (A-side)
__device__ __align__(128) __nv_bfloat16 g_wp[4][(size_t)D_*KP];   // W packed transposed [n][3k] (B-side)
__device__ __align__(128) __nv_bfloat16 g_ap[(size_t)BT_*KP];     // attn out packed (A-side)
__device__ float g_q[(size_t)B_*NH_*T_*HD_];
__device__ float g_k[(size_t)B_*NH_*T_*HD_];
__device__ float g_v[(size_t)B_*NH_*T_*HD_];

// ------------------------- PTX helpers (compute_103-safe only) -------------------------
__device__ __forceinline__ uint32_t smem_u32(const void* p) {
    uint32_t a;
    asm("{ .reg .u64 t; cvta.to.shared.u64 t, %1; cvt.u32.u64 %0, t; }" : "=r"(a) : "l"(p));
    return a;
}
__device__ __forceinline__ void cp_async16(uint32_t s, const void* g) {
    asm volatile("cp.async.cg.shared.global [%0], [%1], 16;" :: "r"(s), "l"(g));
}
#define CP_COMMIT() asm volatile("cp.async.commit_group;" ::: "memory")
#define CP_WAIT2()  asm volatile("cp.async.wait_group 2;" ::: "memory")

__device__ __forceinline__ void ldsm4(uint32_t addr, uint32_t r[4]) {
    asm volatile("ldmatrix.sync.aligned.m8n8.x4.shared.b16 {%0,%1,%2,%3}, [%4];"
                 : "=r"(r[0]), "=r"(r[1]), "=r"(r[2]), "=r"(r[3]) : "r"(addr));
}
__device__ __forceinline__ void mma16816(float d[4], const uint32_t a[4], const uint32_t b[2]) {
    asm volatile("mma.sync.aligned.m16n8k16.row.col.f32.bf16.bf16.f32 "
                 "{%0,%1,%2,%3}, {%4,%5,%6,%7}, {%8,%9}, {%0,%1,%2,%3};"
                 : "+f"(d[0]), "+f"(d[1]), "+f"(d[2]), "+f"(d[3])
                 : "r"(a[0]), "r"(a[1]), "r"(a[2]), "r"(a[3]), "r"(b[0]), "r"(b[1]));
}

// ------------------------- pack kernels -------------------------
// A-side per scalar a: (a_hi, a_lo, a_hi); B-side: (b_hi, b_hi, b_lo).
__global__ __launch_bounds__(256) void pack_a_kernel(const float* __restrict__ X)
{
    int idx = blockIdx.x * 256 + threadIdx.x;
    size_t e = (size_t)idx * 4;
    float4 v = reinterpret_cast<const float4*>(X)[idx];
    int m = (int)(e >> 10), k = (int)(e & 1023);
    float vv[4] = {v.x, v.y, v.z, v.w};
    __nv_bfloat16 buf[12];
#pragma unroll
    for (int u = 0; u < 4; u++) {
        __nv_bfloat16 hi = __float2bfloat16(vv[u]);
        float lo = vv[u] - __bfloat162float(hi);
        buf[3*u] = hi; buf[3*u+1] = __float2bfloat16(lo); buf[3*u+2] = hi;
    }
    uint32_t* dst = reinterpret_cast<uint32_t*>(g_xp + (size_t)m * KP + 3*k);
    const uint32_t* src = reinterpret_cast<const uint32_t*>(buf);
#pragma unroll
    for (int t = 0; t < 6; t++) dst[t] = src[t];
}

// Transpose-pack W[k][n] -> g_wp[z][n][3k..] with (hi, hi, lo)
__global__ __launch_bounds__(256) void pack_w_kernel(
    const float* __restrict__ Wq, const float* __restrict__ Wk,
    const float* __restrict__ Wv, const float* __restrict__ Wp)
{
    const float* W = (blockIdx.z == 0) ? Wq : (blockIdx.z == 1) ? Wk :
                     (blockIdx.z == 2) ? Wv : Wp;
    __nv_bfloat16* out = g_wp[blockIdx.z];
    __shared__ float tile[32][33];
    const int tid = threadIdx.x;
    const int n0 = blockIdx.x * 32, k0 = blockIdx.y * 32;
#pragma unroll
    for (int i = 0; i < 4; i++) {
        int kk = (tid >> 5) + i * 8;
        tile[kk][tid & 31] = W[(size_t)(k0 + kk) * D_ + n0 + (tid & 31)];
    }
    __syncthreads();
#pragma unroll
    for (int i = 0; i < 4; i++) {
        int nn = (tid >> 5) + i * 8;
        int kl = tid & 31;
        float v = tile[kl][nn];
        __nv_bfloat16 hi = __float2bfloat16(v);
        float lo = v - __bfloat162float(hi);
        size_t base = (size_t)(n0 + nn) * KP + 3 * (k0 + kl);
        out[base] = hi; out[base + 1] = hi; out[base + 2] = __float2bfloat16(lo);
    }
}

// ------------------------- HMMA GEMM (128x128, BK=32, 4-stage cp.async) -------------------------
#define STAGE_BYTES 16384   // A 8KB + B 8KB
#define GSMEM (4 * STAGE_BYTES)
#define NKITER (KP / 32)    // 96

// smem tile row = 64B (32 bf16), granule swizzle: g ^= (r>>1)&3  -> conflict-free ldsm & stores
__device__ __forceinline__ uint32_t sw_off(int r, int g) {
    return (uint32_t)(r * 64 + ((g ^ ((r >> 1) & 3)) << 4));
}

__device__ __forceinline__ void load_stage(uint32_t sbuf,
                                           const __nv_bfloat16* __restrict__ A,
                                           const __nv_bfloat16* __restrict__ B,
                                           int kelem)
{
    const int tid = threadIdx.x;
#pragma unroll
    for (int i = 0; i < 4; i++) {
        int ch = tid + i * 256;                 // 0..1023
        int r = (ch & 511) >> 2;
        int g = ch & 3;
        const __nv_bfloat16* base = (ch & 512) ? B : A;
        uint32_t dst = sbuf + sw_off(r, g) + ((ch & 512) ? 8192u : 0u);
        cp_async16(dst, base + (size_t)r * KP + kelem + g * 8);
    }
}

// acc[mt][nt][4]: warp tile 32(M) x 64(N): 2 m16 x 8 n8
__device__ __forceinline__ void gemm_main(uint32_t smem,
                                          const __nv_bfloat16* __restrict__ A,
                                          const __nv_bfloat16* __restrict__ B,
                                          float acc[2][8][4])
{
    const int tid = threadIdx.x, lane = tid & 31, wid = tid >> 5;
    const int wm = (wid & 3) * 32, wn = (wid >> 2) * 64;

    for (int s = 0; s < 3; s++) { load_stage(smem + s * STAGE_BYTES, A, B, s * 32); CP_COMMIT(); }

    const int rA = wm + (lane & 15);
    const int rB = wn + (lane & 15);
    const int kgl = (lane >> 4) & 1;

    for (int ks = 0; ks < NKITER; ks++) {
        CP_WAIT2();
        __syncthreads();
        if (ks + 3 < NKITER)
            load_stage(smem + ((ks + 3) & 3) * STAGE_BYTES, A, B, (ks + 3) * 32);
        CP_COMMIT();

        uint32_t aS = smem + (ks & 3) * STAGE_BYTES;
        uint32_t bS = aS + 8192;
#pragma unroll
        for (int kh = 0; kh < 2; kh++) {
            const int kg = kh * 2 + kgl;
            uint32_t a[2][4], b[4][4];
#pragma unroll
            for (int mt = 0; mt < 2; mt++)
                ldsm4(aS + sw_off(rA + mt * 16, kg), a[mt]);
#pragma unroll
            for (int ng = 0; ng < 4; ng++)
                ldsm4(bS + sw_off(rB + ng * 16, kg), b[ng]);
#pragma unroll
            for (int mt = 0; mt < 2; mt++)
#pragma unroll
                for (int ng = 0; ng < 4; ng++) {
                    uint32_t b0[2] = {b[ng][0], b[ng][2]};
                    uint32_t b1[2] = {b[ng][1], b[ng][3]};
                    mma16816(acc[mt][ng * 2 + 0], a[mt], b0);
                    mma16816(acc[mt][ng * 2 + 1], a[mt], b1);
                }
        }
    }
}

__global__ __launch_bounds__(256, 2) void qkv_gemm(
    const float* __restrict__ bq, const float* __restrict__ bk, const float* __restrict__ bv)
{
    extern __shared__ __align__(128) char smem[];
    uint32_t sb = smem_u32(smem);
    const int z = blockIdx.z;
    const int m0 = blockIdx.y * 128, n0 = blockIdx.x * 128;

    float acc[2][8][4] = {};
    gemm_main(sb, g_xp + (size_t)m0 * KP, g_wp[z] + (size_t)n0 * KP, acc);

    const float* bias = (z == 0) ? bq : (z == 1) ? bk : bv;
    float* out = (z == 0) ? g_q : (z == 1) ? g_k : g_v;

    const int lane = threadIdx.x & 31, wid = threadIdx.x >> 5;
    const int wm = (wid & 3) * 32, wn = (wid >> 2) * 64;
    const int row_l = lane >> 2, col_l = (lane & 3) * 2;
    const int h = (n0 + wn) >> 6;     // whole warp maps into one head (wn multiple of 64)
#pragma unroll
    for (int mt = 0; mt < 2; mt++) {
        int m = m0 + wm + mt * 16 + row_l;
        int bb = m >> 11, t = m & (T_ - 1);
        float* r0p = out + ((size_t)(bb * NH_ + h) * T_ + t) * HD_;
        float* r8p = r0p + 8 * HD_;
#pragma unroll
        for (int nt = 0; nt < 8; nt++) {
            int c = nt * 8 + col_l;
            float2 bi = *reinterpret_cast<const float2*>(&bias[n0 + wn + c]);
            float2 v0 = {acc[mt][nt][0] + bi.x, acc[mt][nt][1] + bi.y};
            float2 v1 = {acc[mt][nt][2] + bi.x, acc[mt][nt][3] + bi.y};
            *reinterpret_cast<float2*>(r0p + c) = v0;
            *reinterpret_cast<float2*>(r8p + c) = v1;
        }
    }
}

__global__ __launch_bounds__(256, 2) void proj_gemm(
    const float* __restrict__ bp, float* __restrict__ outC)
{
    extern __shared__ __align__(128) char smem[];
    uint32_t sb = smem_u32(smem);
    const int m0 = blockIdx.y * 128, n0 = blockIdx.x * 128;

    float acc[2][8][4] = {};
    gemm_main(sb, g_ap + (size_t)m0 * KP, g_wp[3] + (size_t)n0 * KP, acc);

    const int lane = threadIdx.x & 31, wid = threadIdx.x >> 5;
    const int wm = (wid & 3) * 32, wn = (wid >> 2) * 64;
    const int row_l = lane >> 2, col_l = (lane & 3) * 2;
#pragma unroll
    for (int mt = 0; mt < 2; mt++) {
        int m = m0 + wm + mt * 16 + row_l;
        float* r0p = outC + (size_t)m * D_;
        float* r8p = r0p + 8 * D_;
#pragma unroll
        for (int nt = 0; nt < 8; nt++) {
            int n = n0 + wn + nt * 8 + col_l;
            float2 bi = *reinterpret_cast<const float2*>(&bp[n]);
            float2 v0 = {acc[mt][nt][0] + bi.x, acc[mt][nt][1] + bi.y};
            float2 v1 = {acc[mt][nt][2] + bi.x, acc[mt][nt][3] + bi.y};
            *reinterpret_cast<float2*>(r0p + n) = v0;
            *reinterpret_cast<float2*>(r8p + n) = v1;
        }
    }
}

// ------------------------- Flash attention (fp32) -------------------------
#define FPAD 65
#define SM_QST 0
#define SM_KST (64*FPAD)
#define SM_PS  (2*64*FPAD)
#define SM_VS  (3*64*FPAD)
#define FLASH_SMEM ((3*64*FPAD + 64*64) * 4)

__global__ __launch_bounds__(256) void flash_kernel()
{
    extern __shared__ float sm[];
    float* QsT = sm + SM_QST;
    float* KsT = sm + SM_KST;
    float* Ps  = sm + SM_PS;
    float* Vs  = sm + SM_VS;

    const int qt = blockIdx.x;
    const int bh = blockIdx.y;
    const float* Qb = g_q + (size_t)bh * T_ * HD_;
    const float* Kb = g_k + (size_t)bh * T_ * HD_;
    const float* Vb = g_v + (size_t)bh * T_ * HD_;

    const int tid = threadIdx.x;
    const int tx = tid & 15, ty = tid >> 4;
    const int r0 = ty * 4, c0 = tx * 4;

#pragma unroll
    for (int i = 0; i < 16; i++) {
        int idx = tid + i * 256;
        int r = idx >> 6, c = idx & 63;
        QsT[c * FPAD + r] = Qb[(size_t)(qt*64 + r) * HD_ + c];
    }

    float o[4][4] = {};
    float mi[4], li[4];
#pragma unroll
    for (int i = 0; i < 4; i++) { mi[i] = -1e30f; li[i] = 0.0f; }

    for (int jt = 0; jt <= qt; jt++) {
        __syncthreads();
#pragma unroll
        for (int i = 0; i < 16; i++) {
            int idx = tid + i * 256;
            int s = idx >> 6, c = idx & 63;
            KsT[c * FPAD + s] = Kb[(size_t)(jt*64 + s) * HD_ + c];
            Vs[s * 64 + c]    = Vb[(size_t)(jt*64 + s) * HD_ + c];
        }
        __syncthreads();

        float acc[4][4] = {};
#pragma unroll 4
        for (int k = 0; k < HD_; k++) {
            float qf[4], kf[4];
#pragma unroll
            for (int i = 0; i < 4; i++) qf[i] = QsT[k * FPAD + r0 + i];
#pragma unroll
            for (int j = 0; j < 4; j++) kf[j] = KsT[k * FPAD + c0 + j];
#pragma unroll
            for (int i = 0; i < 4; i++)
#pragma unroll
                for (int j = 0; j < 4; j++)
                    acc[i][j] = fmaf(qf[i], kf[j], acc[i][j]);
        }

        if (jt == qt) {
#pragma unroll
            for (int i = 0; i < 4; i++)
#pragma unroll
                for (int j = 0; j < 4; j++)
                    if (c0 + j > r0 + i) acc[i][j] = -1e30f;
        }

#pragma unroll
        for (int i = 0; i < 4; i++) {
            float v = fmaxf(fmaxf(acc[i][0], acc[i][1]), fmaxf(acc[i][2], acc[i][3]));
#pragma unroll
            for (int off = 8; off >= 1; off >>= 1)
                v = fmaxf(v, __shfl_xor_sync(0xffffffffu, v, off));
            float mnew = fmaxf(mi[i], v);
            float scale = __expf(mi[i] - mnew);
            float rs = 0.0f;
#pragma unroll
            for (int j = 0; j < 4; j++) {
                float p = __expf(acc[i][j] - mnew);
                acc[i][j] = p;
                rs += p;
            }
#pragma unroll
            for (int off = 8; off >= 1; off >>= 1)
                rs += __shfl_xor_sync(0xffffffffu, rs, off);
            li[i] = li[i] * scale + rs;
            mi[i] = mnew;
#pragma unroll
            for (int j = 0; j < 4; j++) o[i][j] *= scale;
        }

#pragma unroll
        for (int i = 0; i < 4; i++)
#pragma unroll
            for (int j = 0; j < 4; j++)
                Ps[(r0 + i) * FPAD + (c0 + j)] = acc[i][j];
        __syncthreads();

#pragma unroll 4
        for (int s = 0; s < 64; s++) {
            float pf[4], vf[4];
#pragma unroll
            for (int i = 0; i < 4; i++) pf[i] = Ps[(r0 + i) * FPAD + s];
#pragma unroll
            for (int j = 0; j < 4; j++) vf[j] = Vs[s * 64 + c0 + j];
#pragma unroll
            for (int i = 0; i < 4; i++)
#pragma unroll
                for (int j = 0; j < 4; j++)
                    o[i][j] = fmaf(pf[i], vf[j], o[i][j]);
        }
    }

    // Epilogue: write attention output in packed-triple (A-side) form for proj GEMM
    const int bb = bh >> 4, h = bh & 15;
#pragma unroll
    for (int i = 0; i < 4; i++) {
        float inv = 1.0f / li[i];
        int t = qt * 64 + r0 + i;
        size_t m = (size_t)bb * T_ + t;
        __nv_bfloat16 pb[12];
#pragma unroll
        for (int j = 0; j < 4; j++) {
            float v = o[i][j] * inv;
            __nv_bfloat16 hi = __float2bfloat16(v);
            float lo = v - __bfloat162float(hi);
            pb[3*j] = hi; pb[3*j+1] = __float2bfloat16(lo); pb[3*j+2] = hi;
        }
        uint32_t* dst = reinterpret_cast<uint32_t*>(g_ap + m * KP + 3 * (h * 64 + c0));
        const uint32_t* src = reinterpret_cast<const uint32_t*>(pb);
#pragma unroll
        for (int tt = 0; tt < 6; tt++) dst[tt] = src[tt];
    }
}

// ------------------------- launch -------------------------
extern "C" void kernel_launch(void* const* d_in, const int* in_sizes, int n_in,
                              void* d_out, int out_size)
{
    const float* x  = (const float*)d_in[0];
    const float* Wk = (const float*)d_in[1];
    const float* bk = (const float*)d_in[2];
    const float* Wq = (const float*)d_in[3];
    const float* bq = (const float*)d_in[4];
    const float* Wv = (const float*)d_in[5];
    const float* bv = (const float*)d_in[6];
    const float* Wp = (const float*)d_in[7];
    const float* bp = (const float*)d_in[8];
    float* out = (float*)d_out;

    pack_a_kernel<<<(BT_ * D_) / (4 * 256), 256>>>(x);
    pack_w_kernel<<<dim3(32, 32, 4), 256>>>(Wq, Wk, Wv, Wp);

    cudaFuncSetAttribute(qkv_gemm, cudaFuncAttributeMaxDynamicSharedMemorySize, GSMEM);
    cudaFuncSetAttribute(proj_gemm, cudaFuncAttributeMaxDynamicSharedMemorySize, GSMEM);
    cudaFuncSetAttribute(flash_kernel, cudaFuncAttributeMaxDynamicSharedMemorySize, FLASH_SMEM);

    qkv_gemm<<<dim3(8, 64, 3), 256, GSMEM>>>(bq, bk, bv);
    flash_kernel<<<dim3(T_ / 64, B_ * NH_), 256, FLASH_SMEM>>>();
    proj_gemm<<<dim3(8, 64), 256, GSMEM>>>(bp, out);
}

// round 5
// speedup vs baseline: 1.6097x; 1.6097x over previous
#include <cuda_runtime.h>
#include <cuda_bf16.h>
#include <cstdint>
#include <math.h>

#define B_  4
#define T_  2048
#define D_  1024
#define NH_ 16
#define HD_ 64
#define BT_ (B_*T_)
#define KP  3072
#define KPH 192

__device__ __align__(128) __nv_bfloat16 g_xp[(size_t)BT_*KP];
__device__ __align__(128) __nv_bfloat16 g_wp[4][(size_t)D_*KP];
__device__ __align__(128) __nv_bfloat16 g_ap[(size_t)BT_*KP];
__device__ __align__(128) __nv_bfloat16 g_qp[(size_t)B_*NH_*T_*KPH];
__device__ __align__(128) __nv_bfloat16 g_kp[(size_t)B_*NH_*T_*KPH];
__device__ __align__(128) __nv_bfloat16 g_vp[(size_t)B_*NH_*HD_*3*T_];
__device__ float g_v[(size_t)B_*NH_*T_*HD_];

__device__ __forceinline__ uint32_t smem_u32(const void* p) {
    uint32_t a;
    asm("{ .reg .u64 t; cvta.to.shared.u64 t, %1; cvt.u32.u64 %0, t; }" : "=r"(a) : "l"(p));
    return a;
}
__device__ __forceinline__ void cp_async16(uint32_t s, const void* g) {
    asm volatile("cp.async.cg.shared.global [%0], [%1], 16;" :: "r"(s), "l"(g));
}
#define CP_COMMIT() asm volatile("cp.async.commit_group;" ::: "memory")
#define CP_WAIT2()  asm volatile("cp.async.wait_group 2;" ::: "memory")
#define CP_WAIT0()  asm volatile("cp.async.wait_group 0;" ::: "memory")
__device__ __forceinline__ void ldsm4(uint32_t addr, uint32_t r[4]) {
    asm volatile("ldmatrix.sync.aligned.m8n8.x4.shared.b16 {%0,%1,%2,%3}, [%4];"
                 : "=r"(r[0]), "=r"(r[1]), "=r"(r[2]), "=r"(r[3]) : "r"(addr));
}
__device__ __forceinline__ void mma16816(float d[4], const uint32_t a[4], const uint32_t b[2]) {
    asm volatile("mma.sync.aligned.m16n8k16.row.col.f32.bf16.bf16.f32 "
                 "{%0,%1,%2,%3}, {%4,%5,%6,%7}, {%8,%9}, {%0,%1,%2,%3};"
                 : "+f"(d[0]), "+f"(d[1]), "+f"(d[2]), "+f"(d[3])
                 : "r"(a[0]), "r"(a[1]), "r"(a[2]), "r"(a[3]), "r"(b[0]), "r"(b[1]));
}
__device__ __forceinline__ void sts32(uint32_t a, uint32_t v) {
    asm volatile("st.shared.u32 [%0], %1;" :: "r"(a), "r"(v));
}
__device__ __forceinline__ uint32_t bfpair(float x, float y) {
    __nv_bfloat162 t = __floats2bfloat162_rn(x, y);
    return *reinterpret_cast<uint32_t*>(&t);
}
__device__ __forceinline__ float bflo(float x) {
    return x - __bfloat162float(__float2bfloat16(x));
}

// ---------------- pack kernels ----------------
__global__ __launch_bounds__(256) void pack_a_kernel(const float* __restrict__ X)
{
    int idx = blockIdx.x * 256 + threadIdx.x;
    size_t e = (size_t)idx * 4;
    float4 v = reinterpret_cast<const float4*>(X)[idx];
    int m = (int)(e >> 10), k = (int)(e & 1023);
    float vv[4] = {v.x, v.y, v.z, v.w};
    __nv_bfloat16 buf[12];
#pragma unroll
    for (int u = 0; u < 4; u++) {
        __nv_bfloat16 hi = __float2bfloat16(vv[u]);
        buf[3*u] = hi; buf[3*u+1] = __float2bfloat16(vv[u] - __bfloat162float(hi)); buf[3*u+2] = hi;
    }
    uint32_t* dst = reinterpret_cast<uint32_t*>(g_xp + (size_t)m * KP + 3*k);
    const uint32_t* src = reinterpret_cast<const uint32_t*>(buf);
#pragma unroll
    for (int t = 0; t < 6; t++) dst[t] = src[t];
}

__global__ __launch_bounds__(256) void pack_w_kernel(
    const float* __restrict__ Wq, const float* __restrict__ Wk,
    const float* __restrict__ Wv, const float* __restrict__ Wp)
{
    const float* W = (blockIdx.z == 0) ? Wq : (blockIdx.z == 1) ? Wk :
                     (blockIdx.z == 2) ? Wv : Wp;
    __nv_bfloat16* out = g_wp[blockIdx.z];
    __shared__ float tile[32][33];
    const int tid = threadIdx.x;
    const int n0 = blockIdx.x * 32, k0 = blockIdx.y * 32;
#pragma unroll
    for (int i = 0; i < 4; i++) {
        int kk = (tid >> 5) + i * 8;
        tile[kk][tid & 31] = W[(size_t)(k0 + kk) * D_ + n0 + (tid & 31)];
    }
    __syncthreads();
#pragma unroll
    for (int i = 0; i < 4; i++) {
        int nn = (tid >> 5) + i * 8, kl = tid & 31;
        float v = tile[kl][nn];
        __nv_bfloat16 hi = __float2bfloat16(v);
        size_t base = (size_t)(n0 + nn) * KP + 3 * (k0 + kl);
        out[base] = hi; out[base+1] = hi; out[base+2] = __float2bfloat16(v - __bfloat162float(hi));
    }
}

// V transpose-pack: g_v[bh][s][c] -> g_vp[bh][c][jt*192 + grp*96 + (Vh|Vl|Vh)]
__global__ __launch_bounds__(256) void pack_v_kernel()
{
    __shared__ float tile[64][65];
    const int tl = blockIdx.x, bh = blockIdx.y;
    const float* src = g_v + ((size_t)bh * T_ + tl * 64) * HD_;
    const int tid = threadIdx.x;
#pragma unroll
    for (int i = 0; i < 16; i++) {
        int idx = tid + i * 256;
        tile[idx >> 6][idx & 63] = src[(idx >> 6) * HD_ + (idx & 63)];
    }
    __syncthreads();
    __nv_bfloat16* dstb = g_vp + (size_t)bh * HD_ * 3 * T_ + (size_t)tl * 192;
#pragma unroll
    for (int i = 0; i < 16; i++) {
        int idx = tid + i * 256;
        int c = idx >> 6, s = idx & 63;
        int grp = s >> 5, sl = s & 31;
        float v = tile[s][c];
        __nv_bfloat16 hi = __float2bfloat16(v);
        __nv_bfloat16* dr = dstb + (size_t)c * 3 * T_ + grp * 96;
        dr[sl] = hi; dr[32+sl] = __float2bfloat16(v - __bfloat162float(hi)); dr[64+sl] = hi;
    }
}

// ---------------- HMMA GEMM (128x128, BK=32) ----------------
#define STAGE_BYTES 16384
#define GSMEM (4 * STAGE_BYTES)
#define NKITER (KP / 32)

__device__ __forceinline__ uint32_t sw_off(int r, int g) {
    return (uint32_t)(r * 64 + ((g ^ ((r >> 1) & 3)) << 4));
}
__device__ __forceinline__ void load_stage(uint32_t sbuf,
                                           const __nv_bfloat16* __restrict__ A,
                                           const __nv_bfloat16* __restrict__ B, int kelem)
{
    const int tid = threadIdx.x;
#pragma unroll
    for (int i = 0; i < 4; i++) {
        int ch = tid + i * 256;
        int r = (ch & 511) >> 2, g = ch & 3;
        const __nv_bfloat16* base = (ch & 512) ? B : A;
        cp_async16(sbuf + sw_off(r, g) + ((ch & 512) ? 8192u : 0u),
                   base + (size_t)r * KP + kelem + g * 8);
    }
}
__device__ __forceinline__ void gemm_main(uint32_t smem,
                                          const __nv_bfloat16* __restrict__ A,
                                          const __nv_bfloat16* __restrict__ B,
                                          float acc[2][8][4])
{
    const int tid = threadIdx.x, lane = tid & 31, wid = tid >> 5;
    const int wm = (wid & 3) * 32, wn = (wid >> 2) * 64;
    for (int s = 0; s < 3; s++) { load_stage(smem + s * STAGE_BYTES, A, B, s * 32); CP_COMMIT(); }
    const int rA = wm + (lane & 15), rB = wn + (lane & 15), kgl = (lane >> 4) & 1;
    for (int ks = 0; ks < NKITER; ks++) {
        CP_WAIT2();
        __syncthreads();
        if (ks + 3 < NKITER) load_stage(smem + ((ks + 3) & 3) * STAGE_BYTES, A, B, (ks + 3) * 32);
        CP_COMMIT();
        uint32_t aS = smem + (ks & 3) * STAGE_BYTES, bS = aS + 8192;
#pragma unroll
        for (int kh = 0; kh < 2; kh++) {
            const int kg = kh * 2 + kgl;
            uint32_t a[2][4], b[4][4];
#pragma unroll
            for (int mt = 0; mt < 2; mt++) ldsm4(aS + sw_off(rA + mt * 16, kg), a[mt]);
#pragma unroll
            for (int ng = 0; ng < 4; ng++) ldsm4(bS + sw_off(rB + ng * 16, kg), b[ng]);
#pragma unroll
            for (int mt = 0; mt < 2; mt++)
#pragma unroll
                for (int ng = 0; ng < 4; ng++) {
                    uint32_t b0[2] = {b[ng][0], b[ng][2]};
                    uint32_t b1[2] = {b[ng][1], b[ng][3]};
                    mma16816(acc[mt][ng * 2 + 0], a[mt], b0);
                    mma16816(acc[mt][ng * 2 + 1], a[mt], b1);
                }
        }
    }
}

__global__ __launch_bounds__(256, 2) void qkv_gemm(
    const float* __restrict__ bq, const float* __restrict__ bk, const float* __restrict__ bv)
{
    extern __shared__ __align__(128) char smem[];
    uint32_t sb = smem_u32(smem);
    const int z = blockIdx.z;
    const int m0 = blockIdx.y * 128, n0 = blockIdx.x * 128;
    float acc[2][8][4] = {};
    gemm_main(sb, g_xp + (size_t)m0 * KP, g_wp[z] + (size_t)n0 * KP, acc);

    const float* bias = (z == 0) ? bq : (z == 1) ? bk : bv;
    const int lane = threadIdx.x & 31, wid = threadIdx.x >> 5;
    const int wm = (wid & 3) * 32, wn = (wid >> 2) * 64;
    const int row_l = lane >> 2, col_l = (lane & 3) * 2;
    const int h = (n0 + wn) >> 6;

    if (z <= 1) {
        __nv_bfloat16* dstp = (z == 0) ? g_qp : g_kp;
#pragma unroll
        for (int mt = 0; mt < 2; mt++) {
            int mr = m0 + wm + mt * 16 + row_l;
            int bb = mr >> 11, t = mr & (T_ - 1);
            uint32_t* r0p = reinterpret_cast<uint32_t*>(dstp + ((size_t)(bb*NH_+h)*T_ + t) * KPH);
            uint32_t* r8p = r0p + 8 * (KPH / 2);
#pragma unroll
            for (int nt = 0; nt < 8; nt++) {
                int c = nt * 8 + col_l;
                float bx = bias[n0+wn+c], by = bias[n0+wn+c+1];
                float v0x = acc[mt][nt][0]+bx, v0y = acc[mt][nt][1]+by;
                float v1x = acc[mt][nt][2]+bx, v1y = acc[mt][nt][3]+by;
                uint32_t h0 = bfpair(v0x, v0y), l0 = bfpair(bflo(v0x), bflo(v0y));
                uint32_t h1 = bfpair(v1x, v1y), l1 = bfpair(bflo(v1x), bflo(v1y));
                int ci = nt * 4 + (lane & 3);
                if (z == 0) {
                    r0p[ci]=h0; r0p[32+ci]=l0; r0p[64+ci]=h0;
                    r8p[ci]=h1; r8p[32+ci]=l1; r8p[64+ci]=h1;
                } else {
                    r0p[ci]=h0; r0p[32+ci]=h0; r0p[64+ci]=l0;
                    r8p[ci]=h1; r8p[32+ci]=h1; r8p[64+ci]=l1;
                }
            }
        }
    } else {
#pragma unroll
        for (int mt = 0; mt < 2; mt++) {
            int mr = m0 + wm + mt * 16 + row_l;
            int bb = mr >> 11, t = mr & (T_ - 1);
            float* r0p = g_v + ((size_t)(bb*NH_+h)*T_ + t) * HD_;
            float* r8p = r0p + 8 * HD_;
#pragma unroll
            for (int nt = 0; nt < 8; nt++) {
                int c = nt * 8 + col_l;
                float2 bi = *reinterpret_cast<const float2*>(&bias[n0+wn+c]);
                float2 v0 = {acc[mt][nt][0]+bi.x, acc[mt][nt][1]+bi.y};
                float2 v1 = {acc[mt][nt][2]+bi.x, acc[mt][nt][3]+bi.y};
                *reinterpret_cast<float2*>(r0p + c) = v0;
                *reinterpret_cast<float2*>(r8p + c) = v1;
            }
        }
    }
}

__global__ __launch_bounds__(256, 2) void proj_gemm(const float* __restrict__ bp, float* __restrict__ outC)
{
    extern __shared__ __align__(128) char smem[];
    uint32_t sb = smem_u32(smem);
    const int m0 = blockIdx.y * 128, n0 = blockIdx.x * 128;
    float acc[2][8][4] = {};
    gemm_main(sb, g_ap + (size_t)m0 * KP, g_wp[3] + (size_t)n0 * KP, acc);
    const int lane = threadIdx.x & 31, wid = threadIdx.x >> 5;
    const int wm = (wid & 3) * 32, wn = (wid >> 2) * 64;
    const int row_l = lane >> 2, col_l = (lane & 3) * 2;
#pragma unroll
    for (int mt = 0; mt < 2; mt++) {
        int m = m0 + wm + mt * 16 + row_l;
        float* r0p = outC + (size_t)m * D_;
        float* r8p = r0p + 8 * D_;
#pragma unroll
        for (int nt = 0; nt < 8; nt++) {
            int n = n0 + wn + nt * 8 + col_l;
            float2 bi = *reinterpret_cast<const float2*>(&bp[n]);
            float2 v0 = {acc[mt][nt][0]+bi.x, acc[mt][nt][1]+bi.y};
            float2 v1 = {acc[mt][nt][2]+bi.x, acc[mt][nt][3]+bi.y};
            *reinterpret_cast<float2*>(r0p + n) = v0;
            *reinterpret_cast<float2*>(r8p + n) = v1;
        }
    }
}

// ---------------- HMMA flash ----------------
#define FQS 0
#define FKS 49152
#define FVS 98304
#define FPS 147456
#define FML (FPS + 32768)
#define FLASH_SMEM 196608

__device__ __forceinline__ uint32_t off384(int r, int g) {
    return (uint32_t)(r * 384 + ((g ^ (r & 7)) << 4));
}
__device__ __forceinline__ void f_kv(uint32_t sb, const char* gk, const char* gv, int jt, int buf)
{
    const int tid = threadIdx.x;
    uint32_t ks = sb + FKS + buf * 24576, vs = sb + FVS + buf * 24576;
#pragma unroll
    for (int i = 0; i < 6; i++) {
        int ch = tid + i * 256;
        int r = ch / 24, gr = ch % 24;
        cp_async16(ks + off384(r, gr), gk + ((size_t)(jt*64 + r)*192 + gr*8) * 2);
    }
#pragma unroll
    for (int i = 0; i < 6; i++) {
        int ch = tid + i * 256;
        int r = ch / 24, gr = ch % 24;
        cp_async16(vs + off384(r, gr), gv + ((size_t)r*3*T_ + jt*192 + gr*8) * 2);
    }
}

__global__ void __launch_bounds__(256, 1) flash_mma()
{
    extern __shared__ __align__(128) char sm[];
    uint32_t sb = smem_u32(sm);
    const int qt = (T_/128 - 1) - blockIdx.x;
    const int bh = blockIdx.y;
    const int tid = threadIdx.x, lane = tid & 31, w = tid >> 5;
    const int wm = (w & 3) * 32, g = w >> 2;
    const int rowq = lane >> 2, colq = (lane & 3) * 2;
    const int rA = wm + (lane & 15), kgl = (lane >> 4) & 1;

    const char* gq = (const char*)(g_qp + ((size_t)bh*T_ + (size_t)qt*128) * KPH);
    const char* gk = (const char*)(g_kp + (size_t)bh*T_*KPH);
    const char* gv = (const char*)(g_vp + (size_t)bh*HD_*3*T_);

#pragma unroll
    for (int i = 0; i < 12; i++) {
        int ch = tid + i * 256;
        int r = ch / 24, gr = ch % 24;
        cp_async16(sb + FQS + off384(r, gr), gq + ((size_t)r*192 + gr*8) * 2);
    }
    f_kv(sb, gk, gv, 0, 0);
    CP_COMMIT();

    float O[2][8][4] = {};
    float mr[2][2] = {{-1e30f,-1e30f},{-1e30f,-1e30f}};
    float lr[2][2] = {{0.f,0.f},{0.f,0.f}};

    const int njt = 2 * qt + 2;
    for (int jt = 0; jt < njt; jt++) {
        const int buf = jt & 1;
        CP_WAIT0();
        __syncthreads();
        if (jt + 1 < njt) { f_kv(sb, gk, gv, jt + 1, buf ^ 1); CP_COMMIT(); }

        // S = Q K^T : warp rows wm..+31, keys g*32..+31, k'=192
        float s[2][4][4] = {};
        {
            uint32_t kS = sb + FKS + buf * 24576;
            const int rB = g * 32 + (lane & 15);
#pragma unroll
            for (int j = 0; j < 12; j++) {
                int gr = 2 * j + kgl;
                uint32_t a[2][4], b[2][4];
                ldsm4(sb + FQS + off384(rA, gr), a[0]);
                ldsm4(sb + FQS + off384(rA + 16, gr), a[1]);
                ldsm4(kS + off384(rB, gr), b[0]);
                ldsm4(kS + off384(rB + 16, gr), b[1]);
#pragma unroll
                for (int mt = 0; mt < 2; mt++)
#pragma unroll
                    for (int kk = 0; kk < 2; kk++) {
                        uint32_t p0[2] = {b[kk][0], b[kk][2]};
                        uint32_t p1[2] = {b[kk][1], b[kk][3]};
                        mma16816(s[mt][kk * 2 + 0], a[mt], p0);
                        mma16816(s[mt][kk * 2 + 1], a[mt], p1);
                    }
            }
        }
        if (jt >= 2 * qt) {
            const int rg0 = qt * 128 + wm + rowq;
            const int cg0 = jt * 64 + g * 32 + colq;
#pragma unroll
            for (int mt = 0; mt < 2; mt++)
#pragma unroll
                for (int nt = 0; nt < 4; nt++)
#pragma unroll
                    for (int e = 0; e < 4; e++)
                        if (cg0 + nt * 8 + (e & 1) > rg0 + mt * 16 + (e >> 1) * 8)
                            s[mt][nt][e] = -1e30f;
        }
        float psc[2][2];
#pragma unroll
        for (int mt = 0; mt < 2; mt++)
#pragma unroll
            for (int rg = 0; rg < 2; rg++) {
                float tm = -1e30f;
#pragma unroll
                for (int nt = 0; nt < 4; nt++)
                    tm = fmaxf(tm, fmaxf(s[mt][nt][rg*2], s[mt][nt][rg*2+1]));
                tm = fmaxf(tm, __shfl_xor_sync(0xffffffffu, tm, 1));
                tm = fmaxf(tm, __shfl_xor_sync(0xffffffffu, tm, 2));
                float mn = fmaxf(mr[mt][rg], tm);
                float sc = __expf(mr[mt][rg] - mn);
                float rs = 0.0f;
#pragma unroll
                for (int nt = 0; nt < 4; nt++) {
                    float p0 = __expf(s[mt][nt][rg*2] - mn);
                    float p1 = __expf(s[mt][nt][rg*2+1] - mn);
                    s[mt][nt][rg*2] = p0; s[mt][nt][rg*2+1] = p1;
                    rs += p0 + p1;
                }
                rs += __shfl_xor_sync(0xffffffffu, rs, 1);
                rs += __shfl_xor_sync(0xffffffffu, rs, 2);
                lr[mt][rg] = lr[mt][rg] * sc + rs;
                mr[mt][rg] = mn;
                psc[mt][rg] = sc;
            }
#pragma unroll
        for (int mt = 0; mt < 2; mt++)
#pragma unroll
            for (int ot = 0; ot < 8; ot++) {
                O[mt][ot][0] *= psc[mt][0]; O[mt][ot][1] *= psc[mt][0];
                O[mt][ot][2] *= psc[mt][1]; O[mt][ot][3] *= psc[mt][1];
            }
        // stage P = [Ph|Ph|Pl] into warp's granules 12g..12g+11
        {
            const uint32_t ps = sb + FPS;
            const int rem = (lane & 3) * 4;
#pragma unroll
            for (int mt = 0; mt < 2; mt++)
#pragma unroll
                for (int rg = 0; rg < 2; rg++) {
                    int r = wm + mt * 16 + rowq + rg * 8;
#pragma unroll
                    for (int nt = 0; nt < 4; nt++) {
                        float p0 = s[mt][nt][rg*2], p1 = s[mt][nt][rg*2+1];
                        uint32_t hh = bfpair(p0, p1);
                        uint32_t ll = bfpair(bflo(p0), bflo(p1));
                        sts32(ps + off384(r, 12*g + nt) + rem, hh);
                        sts32(ps + off384(r, 12*g + 4 + nt) + rem, hh);
                        sts32(ps + off384(r, 12*g + 8 + nt) + rem, ll);
                    }
                }
        }
        __syncwarp();
        // O += P V : k'=96 in granules 12g.., B = V dims 0..63
        {
            uint32_t vS = sb + FVS + buf * 24576;
            const int rV = lane & 15;
#pragma unroll
            for (int j = 0; j < 6; j++) {
                int gr = 12 * g + 2 * j + kgl;
                uint32_t a[2][4], b[4][4];
                ldsm4(sb + FPS + off384(rA, gr), a[0]);
                ldsm4(sb + FPS + off384(rA + 16, gr), a[1]);
#pragma unroll
                for (int ng = 0; ng < 4; ng++) ldsm4(vS + off384(rV + ng * 16, gr), b[ng]);
#pragma unroll
                for (int mt = 0; mt < 2; mt++)
#pragma unroll
                    for (int ng = 0; ng < 4; ng++) {
                        uint32_t b0[2] = {b[ng][0], b[ng][2]};
                        uint32_t b1[2] = {b[ng][1], b[ng][3]};
                        mma16816(O[mt][ng * 2 + 0], a[mt], b0);
                        mma16816(O[mt][ng * 2 + 1], a[mt], b1);
                    }
            }
        }
    }
    // merge halves: g=1 dumps to smem, g=0 combines + writes packed g_ap
    __syncthreads();
    if (g == 1) {
#pragma unroll
        for (int mt = 0; mt < 2; mt++)
#pragma unroll
            for (int rg = 0; rg < 2; rg++) {
                int r = wm + mt * 16 + rowq + rg * 8;
                if ((lane & 3) == 0)
                    *reinterpret_cast<float2*>(sm + FML + r * 8) = make_float2(mr[mt][rg], lr[mt][rg]);
#pragma unroll
                for (int nt = 0; nt < 8; nt++) {
                    int c = nt * 8 + colq;
                    *reinterpret_cast<float2*>(sm + FPS + (r * 64 + c) * 4) =
                        make_float2(O[mt][nt][rg*2], O[mt][nt][rg*2+1]);
                }
            }
    }
    __syncthreads();
    if (g == 0) {
        const int h = bh & 15, bb = bh >> 4;
#pragma unroll
        for (int mt = 0; mt < 2; mt++)
#pragma unroll
            for (int rg = 0; rg < 2; rg++) {
                int rl = wm + mt * 16 + rowq + rg * 8;
                float2 ml1 = *reinterpret_cast<float2*>(sm + FML + rl * 8);
                float M = fmaxf(mr[mt][rg], ml1.x);
                float sc0 = __expf(mr[mt][rg] - M), sc1 = __expf(ml1.x - M);
                float inv = 1.0f / (lr[mt][rg] * sc0 + ml1.y * sc1);
                int t = qt * 128 + rl;
                uint32_t* dst = reinterpret_cast<uint32_t*>(
                    g_ap + ((size_t)bb * T_ + t) * KP + 3 * (h * 64));
#pragma unroll
                for (int nt = 0; nt < 8; nt++) {
                    int c = nt * 8 + colq;
                    float2 o1 = *reinterpret_cast<float2*>(sm + FPS + (rl * 64 + c) * 4);
                    float v0 = (O[mt][nt][rg*2] * sc0 + o1.x * sc1) * inv;
                    float v1 = (O[mt][nt][rg*2+1] * sc0 + o1.y * sc1) * inv;
                    uint32_t* d = dst + (3 * c) / 2;
                    d[0] = bfpair(v0, bflo(v0));
                    d[1] = bfpair(v0, v1);
                    d[2] = bfpair(bflo(v1), v1);
                }
            }
    }
}

// ---------------- launch ----------------
extern "C" void kernel_launch(void* const* d_in, const int* in_sizes, int n_in,
                              void* d_out, int out_size)
{
    const float* x  = (const float*)d_in[0];
    const float* Wk = (const float*)d_in[1];
    const float* bk = (const float*)d_in[2];
    const float* Wq = (const float*)d_in[3];
    const float* bq = (const float*)d_in[4];
    const float* Wv = (const float*)d_in[5];
    const float* bv = (const float*)d_in[6];
    const float* Wp = (const float*)d_in[7];
    const float* bp = (const float*)d_in[8];
    float* out = (float*)d_out;

    pack_a_kernel<<<(BT_ * D_) / (4 * 256), 256>>>(x);
    pack_w_kernel<<<dim3(32, 32, 4), 256>>>(Wq, Wk, Wv, Wp);

    cudaFuncSetAttribute(qkv_gemm, cudaFuncAttributeMaxDynamicSharedMemorySize, GSMEM);
    cudaFuncSetAttribute(proj_gemm, cudaFuncAttributeMaxDynamicSharedMemorySize, GSMEM);
    cudaFuncSetAttribute(flash_mma, cudaFuncAttributeMaxDynamicSharedMemorySize, FLASH_SMEM);

    qkv_gemm<<<dim3(8, 64, 3), 256, GSMEM>>>(bq, bk, bv);
    pack_v_kernel<<<dim3(T_ / 64, B_ * NH_), 256>>>();
    flash_mma<<<dim3(T_ / 128, B_ * NH_), 256, FLASH_SMEM>>>();
    proj_gemm<<<dim3(8, 64), 256, GSMEM>>>(bp, out);
}

// round 6
// speedup vs baseline: 1.6673x; 1.0358x over previous
#include <cuda_runtime.h>
#include <cuda_bf16.h>
#include <cstdint>
#include <math.h>

#define B_  4
#define T_  2048
#define D_  1024
#define NH_ 16
#define HD_ 64
#define BT_ (B_*T_)
#define KP  3072
#define KPH 192

__device__ __align__(128) __nv_bfloat16 g_xp[(size_t)BT_*KP];
__device__ __align__(128) __nv_bfloat16 g_wp[4][(size_t)D_*KP];
__device__ __align__(128) __nv_bfloat16 g_ap[(size_t)BT_*KP];
__device__ __align__(128) __nv_bfloat16 g_qp[(size_t)B_*NH_*T_*KPH];
__device__ __align__(128) __nv_bfloat16 g_kp[(size_t)B_*NH_*T_*KPH];
__device__ __align__(128) __nv_bfloat16 g_vp[(size_t)B_*NH_*HD_*3*T_];
__device__ float g_v[(size_t)B_*NH_*T_*HD_];

__device__ __forceinline__ uint32_t smem_u32(const void* p) {
    uint32_t a;
    asm("{ .reg .u64 t; cvta.to.shared.u64 t, %1; cvt.u32.u64 %0, t; }" : "=r"(a) : "l"(p));
    return a;
}
__device__ __forceinline__ void cp_async16(uint32_t s, const void* g) {
    asm volatile("cp.async.cg.shared.global [%0], [%1], 16;" :: "r"(s), "l"(g));
}
#define CP_COMMIT() asm volatile("cp.async.commit_group;" ::: "memory")
#define CP_WAIT2()  asm volatile("cp.async.wait_group 2;" ::: "memory")
#define CP_WAIT0()  asm volatile("cp.async.wait_group 0;" ::: "memory")
__device__ __forceinline__ void ldsm4(uint32_t addr, uint32_t r[4]) {
    asm volatile("ldmatrix.sync.aligned.m8n8.x4.shared.b16 {%0,%1,%2,%3}, [%4];"
                 : "=r"(r[0]), "=r"(r[1]), "=r"(r[2]), "=r"(r[3]) : "r"(addr));
}
__device__ __forceinline__ void mma16816(float d[4], const uint32_t a[4], const uint32_t b[2]) {
    asm volatile("mma.sync.aligned.m16n8k16.row.col.f32.bf16.bf16.f32 "
                 "{%0,%1,%2,%3}, {%4,%5,%6,%7}, {%8,%9}, {%0,%1,%2,%3};"
                 : "+f"(d[0]), "+f"(d[1]), "+f"(d[2]), "+f"(d[3])
                 : "r"(a[0]), "r"(a[1]), "r"(a[2]), "r"(a[3]), "r"(b[0]), "r"(b[1]));
}
__device__ __forceinline__ uint32_t bfpair(float x, float y) {
    __nv_bfloat162 t = __floats2bfloat162_rn(x, y);
    return *reinterpret_cast<uint32_t*>(&t);
}
__device__ __forceinline__ float bflo(float x) {
    return x - __bfloat162float(__float2bfloat16(x));
}

// ---------------- pack kernels ----------------
__global__ __launch_bounds__(256) void pack_a_kernel(const float* __restrict__ X)
{
    int idx = blockIdx.x * 256 + threadIdx.x;
    size_t e = (size_t)idx * 4;
    float4 v = reinterpret_cast<const float4*>(X)[idx];
    int m = (int)(e >> 10), k = (int)(e & 1023);
    float vv[4] = {v.x, v.y, v.z, v.w};
    __nv_bfloat16 buf[12];
#pragma unroll
    for (int u = 0; u < 4; u++) {
        __nv_bfloat16 hi = __float2bfloat16(vv[u]);
        buf[3*u] = hi; buf[3*u+1] = __float2bfloat16(vv[u] - __bfloat162float(hi)); buf[3*u+2] = hi;
    }
    uint32_t* dst = reinterpret_cast<uint32_t*>(g_xp + (size_t)m * KP + 3*k);
    const uint32_t* src = reinterpret_cast<const uint32_t*>(buf);
#pragma unroll
    for (int t = 0; t < 6; t++) dst[t] = src[t];
}

__global__ __launch_bounds__(256) void pack_w_kernel(
    const float* __restrict__ Wq, const float* __restrict__ Wk,
    const float* __restrict__ Wv, const float* __restrict__ Wp)
{
    const float* W = (blockIdx.z == 0) ? Wq : (blockIdx.z == 1) ? Wk :
                     (blockIdx.z == 2) ? Wv : Wp;
    __nv_bfloat16* out = g_wp[blockIdx.z];
    __shared__ float tile[32][33];
    const int tid = threadIdx.x;
    const int n0 = blockIdx.x * 32, k0 = blockIdx.y * 32;
#pragma unroll
    for (int i = 0; i < 4; i++) {
        int kk = (tid >> 5) + i * 8;
        tile[kk][tid & 31] = W[(size_t)(k0 + kk) * D_ + n0 + (tid & 31)];
    }
    __syncthreads();
#pragma unroll
    for (int i = 0; i < 4; i++) {
        int nn = (tid >> 5) + i * 8, kl = tid & 31;
        float v = tile[kl][nn];
        __nv_bfloat16 hi = __float2bfloat16(v);
        size_t base = (size_t)(n0 + nn) * KP + 3 * (k0 + kl);
        out[base] = hi; out[base+1] = hi; out[base+2] = __float2bfloat16(v - __bfloat162float(hi));
    }
}

// V transpose-pack: g_v[bh][s][c] -> g_vp[bh][c][jt*192 + grp*96 + (Vh|Vl|Vh)]
__global__ __launch_bounds__(256) void pack_v_kernel()
{
    __shared__ float tile[64][65];
    const int tl = blockIdx.x, bh = blockIdx.y;
    const float* src = g_v + ((size_t)bh * T_ + tl * 64) * HD_;
    const int tid = threadIdx.x;
#pragma unroll
    for (int i = 0; i < 16; i++) {
        int idx = tid + i * 256;
        tile[idx >> 6][idx & 63] = src[(idx >> 6) * HD_ + (idx & 63)];
    }
    __syncthreads();
    __nv_bfloat16* dstb = g_vp + (size_t)bh * HD_ * 3 * T_ + (size_t)tl * 192;
#pragma unroll
    for (int i = 0; i < 16; i++) {
        int idx = tid + i * 256;
        int c = idx >> 6, s = idx & 63;
        int grp = s >> 5, sl = s & 31;
        float v = tile[s][c];
        __nv_bfloat16 hi = __float2bfloat16(v);
        __nv_bfloat16* dr = dstb + (size_t)c * 3 * T_ + grp * 96;
        dr[sl] = hi; dr[32+sl] = __float2bfloat16(v - __bfloat162float(hi)); dr[64+sl] = hi;
    }
}

// ---------------- HMMA GEMM (128x128, BK=32) ----------------
#define STAGE_BYTES 16384
#define GSMEM (4 * STAGE_BYTES)
#define NKITER (KP / 32)

__device__ __forceinline__ uint32_t sw_off(int r, int g) {
    return (uint32_t)(r * 64 + ((g ^ ((r >> 1) & 3)) << 4));
}
__device__ __forceinline__ void load_stage(uint32_t sbuf,
                                           const __nv_bfloat16* __restrict__ A,
                                           const __nv_bfloat16* __restrict__ B, int kelem)
{
    const int tid = threadIdx.x;
#pragma unroll
    for (int i = 0; i < 4; i++) {
        int ch = tid + i * 256;
        int r = (ch & 511) >> 2, g = ch & 3;
        const __nv_bfloat16* base = (ch & 512) ? B : A;
        cp_async16(sbuf + sw_off(r, g) + ((ch & 512) ? 8192u : 0u),
                   base + (size_t)r * KP + kelem + g * 8);
    }
}
__device__ __forceinline__ void gemm_main(uint32_t smem,
                                          const __nv_bfloat16* __restrict__ A,
                                          const __nv_bfloat16* __restrict__ B,
                                          float acc[2][8][4])
{
    const int tid = threadIdx.x, lane = tid & 31, wid = tid >> 5;
    const int wm = (wid & 3) * 32, wn = (wid >> 2) * 64;
    for (int s = 0; s < 3; s++) { load_stage(smem + s * STAGE_BYTES, A, B, s * 32); CP_COMMIT(); }
    const int rA = wm + (lane & 15), rB = wn + (lane & 15), kgl = (lane >> 4) & 1;
    for (int ks = 0; ks < NKITER; ks++) {
        CP_WAIT2();
        __syncthreads();
        if (ks + 3 < NKITER) load_stage(smem + ((ks + 3) & 3) * STAGE_BYTES, A, B, (ks + 3) * 32);
        CP_COMMIT();
        uint32_t aS = smem + (ks & 3) * STAGE_BYTES, bS = aS + 8192;
#pragma unroll
        for (int kh = 0; kh < 2; kh++) {
            const int kg = kh * 2 + kgl;
            uint32_t a[2][4], b[4][4];
#pragma unroll
            for (int mt = 0; mt < 2; mt++) ldsm4(aS + sw_off(rA + mt * 16, kg), a[mt]);
#pragma unroll
            for (int ng = 0; ng < 4; ng++) ldsm4(bS + sw_off(rB + ng * 16, kg), b[ng]);
#pragma unroll
            for (int mt = 0; mt < 2; mt++)
#pragma unroll
                for (int ng = 0; ng < 4; ng++) {
                    uint32_t b0[2] = {b[ng][0], b[ng][2]};
                    uint32_t b1[2] = {b[ng][1], b[ng][3]};
                    mma16816(acc[mt][ng * 2 + 0], a[mt], b0);
                    mma16816(acc[mt][ng * 2 + 1], a[mt], b1);
                }
        }
    }
}

__global__ __launch_bounds__(256, 2) void qkv_gemm(
    const float* __restrict__ bq, const float* __restrict__ bk, const float* __restrict__ bv)
{
    extern __shared__ __align__(128) char smem[];
    uint32_t sb = smem_u32(smem);
    const int z = blockIdx.z;
    const int m0 = blockIdx.y * 128, n0 = blockIdx.x * 128;
    float acc[2][8][4] = {};
    gemm_main(sb, g_xp + (size_t)m0 * KP, g_wp[z] + (size_t)n0 * KP, acc);

    const float* bias = (z == 0) ? bq : (z == 1) ? bk : bv;
    const int lane = threadIdx.x & 31, wid = threadIdx.x >> 5;
    const int wm = (wid & 3) * 32, wn = (wid >> 2) * 64;
    const int row_l = lane >> 2, col_l = (lane & 3) * 2;
    const int h = (n0 + wn) >> 6;

    if (z <= 1) {
        __nv_bfloat16* dstp = (z == 0) ? g_qp : g_kp;
#pragma unroll
        for (int mt = 0; mt < 2; mt++) {
            int mr = m0 + wm + mt * 16 + row_l;
            int bb = mr >> 11, t = mr & (T_ - 1);
            uint32_t* r0p = reinterpret_cast<uint32_t*>(dstp + ((size_t)(bb*NH_+h)*T_ + t) * KPH);
            uint32_t* r8p = r0p + 8 * (KPH / 2);
#pragma unroll
            for (int nt = 0; nt < 8; nt++) {
                int c = nt * 8 + col_l;
                float bx = bias[n0+wn+c], by = bias[n0+wn+c+1];
                float v0x = acc[mt][nt][0]+bx, v0y = acc[mt][nt][1]+by;
                float v1x = acc[mt][nt][2]+bx, v1y = acc[mt][nt][3]+by;
                uint32_t h0 = bfpair(v0x, v0y), l0 = bfpair(bflo(v0x), bflo(v0y));
                uint32_t h1 = bfpair(v1x, v1y), l1 = bfpair(bflo(v1x), bflo(v1y));
                int ci = nt * 4 + (lane & 3);
                if (z == 0) {
                    r0p[ci]=h0; r0p[32+ci]=l0; r0p[64+ci]=h0;
                    r8p[ci]=h1; r8p[32+ci]=l1; r8p[64+ci]=h1;
                } else {
                    r0p[ci]=h0; r0p[32+ci]=h0; r0p[64+ci]=l0;
                    r8p[ci]=h1; r8p[32+ci]=h1; r8p[64+ci]=l1;
                }
            }
        }
    } else {
#pragma unroll
        for (int mt = 0; mt < 2; mt++) {
            int mr = m0 + wm + mt * 16 + row_l;
            int bb = mr >> 11, t = mr & (T_ - 1);
            float* r0p = g_v + ((size_t)(bb*NH_+h)*T_ + t) * HD_;
            float* r8p = r0p + 8 * HD_;
#pragma unroll
            for (int nt = 0; nt < 8; nt++) {
                int c = nt * 8 + col_l;
                float2 bi = *reinterpret_cast<const float2*>(&bias[n0+wn+c]);
                float2 v0 = {acc[mt][nt][0]+bi.x, acc[mt][nt][1]+bi.y};
                float2 v1 = {acc[mt][nt][2]+bi.x, acc[mt][nt][3]+bi.y};
                *reinterpret_cast<float2*>(r0p + c) = v0;
                *reinterpret_cast<float2*>(r8p + c) = v1;
            }
        }
    }
}

__global__ __launch_bounds__(256, 2) void proj_gemm(const float* __restrict__ bp, float* __restrict__ outC)
{
    extern __shared__ __align__(128) char smem[];
    uint32_t sb = smem_u32(smem);
    const int m0 = blockIdx.y * 128, n0 = blockIdx.x * 128;
    float acc[2][8][4] = {};
    gemm_main(sb, g_ap + (size_t)m0 * KP, g_wp[3] + (size_t)n0 * KP, acc);
    const int lane = threadIdx.x & 31, wid = threadIdx.x >> 5;
    const int wm = (wid & 3) * 32, wn = (wid >> 2) * 64;
    const int row_l = lane >> 2, col_l = (lane & 3) * 2;
#pragma unroll
    for (int mt = 0; mt < 2; mt++) {
        int m = m0 + wm + mt * 16 + row_l;
        float* r0p = outC + (size_t)m * D_;
        float* r8p = r0p + 8 * D_;
#pragma unroll
        for (int nt = 0; nt < 8; nt++) {
            int n = n0 + wn + nt * 8 + col_l;
            float2 bi = *reinterpret_cast<const float2*>(&bp[n]);
            float2 v0 = {acc[mt][nt][0]+bi.x, acc[mt][nt][1]+bi.y};
            float2 v1 = {acc[mt][nt][2]+bi.x, acc[mt][nt][3]+bi.y};
            *reinterpret_cast<float2*>(r0p + n) = v0;
            *reinterpret_cast<float2*>(r8p + n) = v1;
        }
    }
}

// ---------------- HMMA flash (register-P) ----------------
#define FQS 0
#define FKS 49152
#define FVS 98304
#define FPS 147456
#define FML (FPS + 32768)
#define FLASH_SMEM (FML + 1024)

__device__ __forceinline__ uint32_t off384(int r, int g) {
    return (uint32_t)(r * 384 + ((g ^ (r & 7)) << 4));
}
__device__ __forceinline__ void f_kv(uint32_t sb, const char* gk, const char* gv, int jt, int buf)
{
    const int tid = threadIdx.x;
    uint32_t ks = sb + FKS + buf * 24576, vs = sb + FVS + buf * 24576;
#pragma unroll
    for (int i = 0; i < 6; i++) {
        int ch = tid + i * 256;
        int r = ch / 24, gr = ch % 24;
        cp_async16(ks + off384(r, gr), gk + ((size_t)(jt*64 + r)*192 + gr*8) * 2);
    }
#pragma unroll
    for (int i = 0; i < 6; i++) {
        int ch = tid + i * 256;
        int r = ch / 24, gr = ch % 24;
        cp_async16(vs + off384(r, gr), gv + ((size_t)r*3*T_ + jt*192 + gr*8) * 2);
    }
}

__global__ void __launch_bounds__(256, 1) flash_mma()
{
    extern __shared__ __align__(128) char sm[];
    uint32_t sb = smem_u32(sm);
    const int qt = (T_/128 - 1) - blockIdx.x;
    const int bh = blockIdx.y;
    const int tid = threadIdx.x, lane = tid & 31, w = tid >> 5;
    const int wm = (w & 3) * 32, g = w >> 2;
    const int rowq = lane >> 2, colq = (lane & 3) * 2;
    const int rA = wm + (lane & 15), kgl = (lane >> 4) & 1;

    const char* gq = (const char*)(g_qp + ((size_t)bh*T_ + (size_t)qt*128) * KPH);
    const char* gk = (const char*)(g_kp + (size_t)bh*T_*KPH);
    const char* gv = (const char*)(g_vp + (size_t)bh*HD_*3*T_);

#pragma unroll
    for (int i = 0; i < 12; i++) {
        int ch = tid + i * 256;
        int r = ch / 24, gr = ch % 24;
        cp_async16(sb + FQS + off384(r, gr), gq + ((size_t)r*192 + gr*8) * 2);
    }
    f_kv(sb, gk, gv, 0, 0);
    CP_COMMIT();

    float O[2][8][4] = {};
    float mr[2][2] = {{-1e30f,-1e30f},{-1e30f,-1e30f}};
    float lr[2][2] = {{0.f,0.f},{0.f,0.f}};

    const int njt = 2 * qt + 2;
    for (int jt = 0; jt < njt; jt++) {
        const int buf = jt & 1;
        CP_WAIT0();
        __syncthreads();
        if (jt + 1 < njt) { f_kv(sb, gk, gv, jt + 1, buf ^ 1); CP_COMMIT(); }

        // last diagonal tile: warps on rows 0..63 are fully masked -> skip
        const bool skip_all = (jt == 2 * qt + 1) && (wm < 64);
        if (skip_all) continue;

        // S = Q K^T : warp rows wm..+31, keys g*32..+31, k'=192
        float s[2][4][4] = {};
        {
            uint32_t kS = sb + FKS + buf * 24576;
            const int rB = g * 32 + (lane & 15);
#pragma unroll
            for (int j = 0; j < 12; j++) {
                int gr = 2 * j + kgl;
                uint32_t a[2][4], b[2][4];
                ldsm4(sb + FQS + off384(rA, gr), a[0]);
                ldsm4(sb + FQS + off384(rA + 16, gr), a[1]);
                ldsm4(kS + off384(rB, gr), b[0]);
                ldsm4(kS + off384(rB + 16, gr), b[1]);
#pragma unroll
                for (int mt = 0; mt < 2; mt++)
#pragma unroll
                    for (int kk = 0; kk < 2; kk++) {
                        uint32_t p0[2] = {b[kk][0], b[kk][2]};
                        uint32_t p1[2] = {b[kk][1], b[kk][3]};
                        mma16816(s[mt][kk * 2 + 0], a[mt], p0);
                        mma16816(s[mt][kk * 2 + 1], a[mt], p1);
                    }
            }
        }
        // causal mask only where the diagonal crosses this warp tile
        if ((jt == 2 * qt && wm < 64) || (jt == 2 * qt + 1 && wm >= 64)) {
            const int rg0 = qt * 128 + wm + rowq;
            const int cg0 = jt * 64 + g * 32 + colq;
#pragma unroll
            for (int mt = 0; mt < 2; mt++)
#pragma unroll
                for (int nt = 0; nt < 4; nt++)
#pragma unroll
                    for (int e = 0; e < 4; e++)
                        if (cg0 + nt * 8 + (e & 1) > rg0 + mt * 16 + (e >> 1) * 8)
                            s[mt][nt][e] = -1e30f;
        }
        float psc[2][2];
#pragma unroll
        for (int mt = 0; mt < 2; mt++)
#pragma unroll
            for (int rg = 0; rg < 2; rg++) {
                float tm = -1e30f;
#pragma unroll
                for (int nt = 0; nt < 4; nt++)
                    tm = fmaxf(tm, fmaxf(s[mt][nt][rg*2], s[mt][nt][rg*2+1]));
                tm = fmaxf(tm, __shfl_xor_sync(0xffffffffu, tm, 1));
                tm = fmaxf(tm, __shfl_xor_sync(0xffffffffu, tm, 2));
                float mn = fmaxf(mr[mt][rg], tm);
                float sc = __expf(mr[mt][rg] - mn);
                float rs = 0.0f;
#pragma unroll
                for (int nt = 0; nt < 4; nt++) {
                    float p0 = __expf(s[mt][nt][rg*2] - mn);
                    float p1 = __expf(s[mt][nt][rg*2+1] - mn);
                    s[mt][nt][rg*2] = p0; s[mt][nt][rg*2+1] = p1;
                    rs += p0 + p1;
                }
                rs += __shfl_xor_sync(0xffffffffu, rs, 1);
                rs += __shfl_xor_sync(0xffffffffu, rs, 2);
                lr[mt][rg] = lr[mt][rg] * sc + rs;
                mr[mt][rg] = mn;
                psc[mt][rg] = sc;
            }
#pragma unroll
        for (int mt = 0; mt < 2; mt++)
#pragma unroll
            for (int ot = 0; ot < 8; ot++) {
                O[mt][ot][0] *= psc[mt][0]; O[mt][ot][1] *= psc[mt][0];
                O[mt][ot][2] *= psc[mt][1]; O[mt][ot][3] *= psc[mt][1];
            }
        // P as in-register A fragments (accumulator layout == A-operand layout)
        uint32_t hiA[2][2][4], loA[2][2][4];
#pragma unroll
        for (int mt = 0; mt < 2; mt++)
#pragma unroll
            for (int j2 = 0; j2 < 2; j2++) {
                const float* s0 = s[mt][2*j2];
                const float* s1 = s[mt][2*j2+1];
                hiA[mt][j2][0] = bfpair(s0[0], s0[1]);
                hiA[mt][j2][1] = bfpair(s0[2], s0[3]);
                hiA[mt][j2][2] = bfpair(s1[0], s1[1]);
                hiA[mt][j2][3] = bfpair(s1[2], s1[3]);
                loA[mt][j2][0] = bfpair(bflo(s0[0]), bflo(s0[1]));
                loA[mt][j2][1] = bfpair(bflo(s0[2]), bflo(s0[3]));
                loA[mt][j2][2] = bfpair(bflo(s1[0]), bflo(s1[1]));
                loA[mt][j2][3] = bfpair(bflo(s1[2]), bflo(s1[3]));
            }
        // O += P V : V cols per group g = [Vh(32)|Vl(32)|Vh(32)] -> A = [Ph,Ph,Pl]
        {
            uint32_t vS = sb + FVS + buf * 24576;
            const int rV = lane & 15;
#pragma unroll
            for (int j = 0; j < 6; j++) {
                int gr = 12 * g + 2 * j + kgl;
                uint32_t b[4][4];
#pragma unroll
                for (int ng = 0; ng < 4; ng++) ldsm4(vS + off384(rV + ng * 16, gr), b[ng]);
#pragma unroll
                for (int mt = 0; mt < 2; mt++) {
                    const uint32_t* a = (j < 4) ? hiA[mt][j & 1] : loA[mt][j & 1];
#pragma unroll
                    for (int ng = 0; ng < 4; ng++) {
                        uint32_t b0[2] = {b[ng][0], b[ng][2]};
                        uint32_t b1[2] = {b[ng][1], b[ng][3]};
                        mma16816(O[mt][ng * 2 + 0], a, b0);
                        mma16816(O[mt][ng * 2 + 1], a, b1);
                    }
                }
            }
        }
    }
    // merge halves: g=1 dumps to smem, g=0 combines + writes packed g_ap
    __syncthreads();
    if (g == 1) {
#pragma unroll
        for (int mt = 0; mt < 2; mt++)
#pragma unroll
            for (int rg = 0; rg < 2; rg++) {
                int r = wm + mt * 16 + rowq + rg * 8;
                if ((lane & 3) == 0)
                    *reinterpret_cast<float2*>(sm + FML + r * 8) = make_float2(mr[mt][rg], lr[mt][rg]);
#pragma unroll
                for (int nt = 0; nt < 8; nt++) {
                    int c = nt * 8 + colq;
                    *reinterpret_cast<float2*>(sm + FPS + (r * 64 + c) * 4) =
                        make_float2(O[mt][nt][rg*2], O[mt][nt][rg*2+1]);
                }
            }
    }
    __syncthreads();
    if (g == 0) {
        const int h = bh & 15, bb = bh >> 4;
#pragma unroll
        for (int mt = 0; mt < 2; mt++)
#pragma unroll
            for (int rg = 0; rg < 2; rg++) {
                int rl = wm + mt * 16 + rowq + rg * 8;
                float2 ml1 = *reinterpret_cast<float2*>(sm + FML + rl * 8);
                float M = fmaxf(mr[mt][rg], ml1.x);
                float sc0 = __expf(mr[mt][rg] - M), sc1 = __expf(ml1.x - M);
                float inv = 1.0f / (lr[mt][rg] * sc0 + ml1.y * sc1);
                int t = qt * 128 + rl;
                uint32_t* dst = reinterpret_cast<uint32_t*>(
                    g_ap + ((size_t)bb * T_ + t) * KP + 3 * (h * 64));
#pragma unroll
                for (int nt = 0; nt < 8; nt++) {
                    int c = nt * 8 + colq;
                    float2 o1 = *reinterpret_cast<float2*>(sm + FPS + (rl * 64 + c) * 4);
                    float v0 = (O[mt][nt][rg*2] * sc0 + o1.x * sc1) * inv;
                    float v1 = (O[mt][nt][rg*2+1] * sc0 + o1.y * sc1) * inv;
                    uint32_t* d = dst + (3 * c) / 2;
                    d[0] = bfpair(v0, bflo(v0));
                    d[1] = bfpair(v0, v1);
                    d[2] = bfpair(bflo(v1), v1);
                }
            }
    }
}

// ---------------- launch ----------------
extern "C" void kernel_launch(void* const* d_in, const int* in_sizes, int n_in,
                              void* d_out, int out_size)
{
    const float* x  = (const float*)d_in[0];
    const float* Wk = (const float*)d_in[1];
    const float* bk = (const float*)d_in[2];
    const float* Wq = (const float*)d_in[3];
    const float* bq = (const float*)d_in[4];
    const float* Wv = (const float*)d_in[5];
    const float* bv = (const float*)d_in[6];
    const float* Wp = (const float*)d_in[7];
    const float* bp = (const float*)d_in[8];
    float* out = (float*)d_out;

    pack_a_kernel<<<(BT_ * D_) / (4 * 256), 256>>>(x);
    pack_w_kernel<<<dim3(32, 32, 4), 256>>>(Wq, Wk, Wv, Wp);

    cudaFuncSetAttribute(qkv_gemm, cudaFuncAttributeMaxDynamicSharedMemorySize, GSMEM);
    cudaFuncSetAttribute(proj_gemm, cudaFuncAttributeMaxDynamicSharedMemorySize, GSMEM);
    cudaFuncSetAttribute(flash_mma, cudaFuncAttributeMaxDynamicSharedMemorySize, FLASH_SMEM);

    qkv_gemm<<<dim3(8, 64, 3), 256, GSMEM>>>(bq, bk, bv);
    pack_v_kernel<<<dim3(T_ / 64, B_ * NH_), 256>>>();
    flash_mma<<<dim3(T_ / 128, B_ * NH_), 256, FLASH_SMEM>>>();
    proj_gemm<<<dim3(8, 64), 256, GSMEM>>>(bp, out);
}

// round 7
// speedup vs baseline: 1.7126x; 1.0272x over previous
#include <cuda_runtime.h>
#include <cuda_bf16.h>
#include <cstdint>
#include <math.h>

#define B_  4
#define T_  2048
#define D_  1024
#define NH_ 16
#define HD_ 64
#define BT_ (B_*T_)
#define KP  3072
#define KPH 128      // flash packed head dim: [h(64)|l(64)]

__device__ __align__(128) __nv_bfloat16 g_xp[(size_t)BT_*KP];
__device__ __align__(128) __nv_bfloat16 g_wp[4][(size_t)D_*KP];
__device__ __align__(128) __nv_bfloat16 g_ap[(size_t)BT_*KP];
__device__ __align__(128) __nv_bfloat16 g_qp[(size_t)B_*NH_*T_*KPH];
__device__ __align__(128) __nv_bfloat16 g_kp[(size_t)B_*NH_*T_*KPH];
__device__ __align__(128) __nv_bfloat16 g_vp[(size_t)B_*NH_*HD_*2*T_];
__device__ float g_v[(size_t)B_*NH_*T_*HD_];

__device__ __forceinline__ uint32_t smem_u32(const void* p) {
    uint32_t a;
    asm("{ .reg .u64 t; cvta.to.shared.u64 t, %1; cvt.u32.u64 %0, t; }" : "=r"(a) : "l"(p));
    return a;
}
__device__ __forceinline__ void cp_async16(uint32_t s, const void* g) {
    asm volatile("cp.async.cg.shared.global [%0], [%1], 16;" :: "r"(s), "l"(g));
}
#define CP_COMMIT() asm volatile("cp.async.commit_group;" ::: "memory")
#define CP_WAIT2()  asm volatile("cp.async.wait_group 2;" ::: "memory")
#define CP_WAIT0()  asm volatile("cp.async.wait_group 0;" ::: "memory")
__device__ __forceinline__ void ldsm4(uint32_t addr, uint32_t r[4]) {
    asm volatile("ldmatrix.sync.aligned.m8n8.x4.shared.b16 {%0,%1,%2,%3}, [%4];"
                 : "=r"(r[0]), "=r"(r[1]), "=r"(r[2]), "=r"(r[3]) : "r"(addr));
}
__device__ __forceinline__ void mma16816(float d[4], const uint32_t a[4], const uint32_t b[2]) {
    asm volatile("mma.sync.aligned.m16n8k16.row.col.f32.bf16.bf16.f32 "
                 "{%0,%1,%2,%3}, {%4,%5,%6,%7}, {%8,%9}, {%0,%1,%2,%3};"
                 : "+f"(d[0]), "+f"(d[1]), "+f"(d[2]), "+f"(d[3])
                 : "r"(a[0]), "r"(a[1]), "r"(a[2]), "r"(a[3]), "r"(b[0]), "r"(b[1]));
}
__device__ __forceinline__ uint32_t bfpair(float x, float y) {
    __nv_bfloat162 t = __floats2bfloat162_rn(x, y);
    return *reinterpret_cast<uint32_t*>(&t);
}
__device__ __forceinline__ float bflo(float x) {
    return x - __bfloat162float(__float2bfloat16(x));
}

// ---------------- pack kernels ----------------
__global__ __launch_bounds__(256) void pack_a_kernel(const float* __restrict__ X)
{
    int idx = blockIdx.x * 256 + threadIdx.x;
    size_t e = (size_t)idx * 4;
    float4 v = reinterpret_cast<const float4*>(X)[idx];
    int m = (int)(e >> 10), k = (int)(e & 1023);
    float vv[4] = {v.x, v.y, v.z, v.w};
    __nv_bfloat16 buf[12];
#pragma unroll
    for (int u = 0; u < 4; u++) {
        __nv_bfloat16 hi = __float2bfloat16(vv[u]);
        buf[3*u] = hi; buf[3*u+1] = __float2bfloat16(vv[u] - __bfloat162float(hi)); buf[3*u+2] = hi;
    }
    uint32_t* dst = reinterpret_cast<uint32_t*>(g_xp + (size_t)m * KP + 3*k);
    const uint32_t* src = reinterpret_cast<const uint32_t*>(buf);
#pragma unroll
    for (int t = 0; t < 6; t++) dst[t] = src[t];
}

__global__ __launch_bounds__(256) void pack_w_kernel(
    const float* __restrict__ Wq, const float* __restrict__ Wk,
    const float* __restrict__ Wv, const float* __restrict__ Wp)
{
    const float* W = (blockIdx.z == 0) ? Wq : (blockIdx.z == 1) ? Wk :
                     (blockIdx.z == 2) ? Wv : Wp;
    __nv_bfloat16* out = g_wp[blockIdx.z];
    __shared__ float tile[32][33];
    const int tid = threadIdx.x;
    const int n0 = blockIdx.x * 32, k0 = blockIdx.y * 32;
#pragma unroll
    for (int i = 0; i < 4; i++) {
        int kk = (tid >> 5) + i * 8;
        tile[kk][tid & 31] = W[(size_t)(k0 + kk) * D_ + n0 + (tid & 31)];
    }
    __syncthreads();
#pragma unroll
    for (int i = 0; i < 4; i++) {
        int nn = (tid >> 5) + i * 8, kl = tid & 31;
        float v = tile[kl][nn];
        __nv_bfloat16 hi = __float2bfloat16(v);
        size_t base = (size_t)(n0 + nn) * KP + 3 * (k0 + kl);
        out[base] = hi; out[base+1] = hi; out[base+2] = __float2bfloat16(v - __bfloat162float(hi));
    }
}

// V transpose-pack: g_v[bh][s][c] -> g_vp[bh][c][jt*128 + grp*64 + (Vh32|Vl32)]
__global__ __launch_bounds__(256) void pack_v_kernel()
{
    __shared__ float tile[64][65];
    const int tl = blockIdx.x, bh = blockIdx.y;
    const float* src = g_v + ((size_t)bh * T_ + tl * 64) * HD_;
    const int tid = threadIdx.x;
#pragma unroll
    for (int i = 0; i < 16; i++) {
        int idx = tid + i * 256;
        tile[idx >> 6][idx & 63] = src[(idx >> 6) * HD_ + (idx & 63)];
    }
    __syncthreads();
    __nv_bfloat16* dstb = g_vp + (size_t)bh * HD_ * 2 * T_ + (size_t)tl * 128;
#pragma unroll
    for (int i = 0; i < 16; i++) {
        int idx = tid + i * 256;
        int c = idx >> 6, s = idx & 63;
        int grp = s >> 5, sl = s & 31;
        float v = tile[s][c];
        __nv_bfloat16 hi = __float2bfloat16(v);
        __nv_bfloat16* dr = dstb + (size_t)c * 2 * T_ + grp * 64;
        dr[sl] = hi; dr[32+sl] = __float2bfloat16(v - __bfloat162float(hi));
    }
}

// ---------------- HMMA GEMM (128x128, BK=32) ----------------
#define STAGE_BYTES 16384
#define GSMEM (4 * STAGE_BYTES)
#define NKITER (KP / 32)

__device__ __forceinline__ uint32_t sw_off(int r, int g) {
    return (uint32_t)(r * 64 + ((g ^ ((r >> 1) & 3)) << 4));
}
__device__ __forceinline__ void load_stage(uint32_t sbuf,
                                           const __nv_bfloat16* __restrict__ A,
                                           const __nv_bfloat16* __restrict__ B, int kelem)
{
    const int tid = threadIdx.x;
#pragma unroll
    for (int i = 0; i < 4; i++) {
        int ch = tid + i * 256;
        int r = (ch & 511) >> 2, g = ch & 3;
        const __nv_bfloat16* base = (ch & 512) ? B : A;
        cp_async16(sbuf + sw_off(r, g) + ((ch & 512) ? 8192u : 0u),
                   base + (size_t)r * KP + kelem + g * 8);
    }
}
__device__ __forceinline__ void gemm_main(uint32_t smem,
                                          const __nv_bfloat16* __restrict__ A,
                                          const __nv_bfloat16* __restrict__ B,
                                          float acc[2][8][4])
{
    const int tid = threadIdx.x, lane = tid & 31, wid = tid >> 5;
    const int wm = (wid & 3) * 32, wn = (wid >> 2) * 64;
    for (int s = 0; s < 3; s++) { load_stage(smem + s * STAGE_BYTES, A, B, s * 32); CP_COMMIT(); }
    const int rA = wm + (lane & 15), rB = wn + (lane & 15), kgl = (lane >> 4) & 1;
    for (int ks = 0; ks < NKITER; ks++) {
        CP_WAIT2();
        __syncthreads();
        if (ks + 3 < NKITER) load_stage(smem + ((ks + 3) & 3) * STAGE_BYTES, A, B, (ks + 3) * 32);
        CP_COMMIT();
        uint32_t aS = smem + (ks & 3) * STAGE_BYTES, bS = aS + 8192;
#pragma unroll
        for (int kh = 0; kh < 2; kh++) {
            const int kg = kh * 2 + kgl;
            uint32_t a[2][4], b[4][4];
#pragma unroll
            for (int mt = 0; mt < 2; mt++) ldsm4(aS + sw_off(rA + mt * 16, kg), a[mt]);
#pragma unroll
            for (int ng = 0; ng < 4; ng++) ldsm4(bS + sw_off(rB + ng * 16, kg), b[ng]);
#pragma unroll
            for (int mt = 0; mt < 2; mt++)
#pragma unroll
                for (int ng = 0; ng < 4; ng++) {
                    uint32_t b0[2] = {b[ng][0], b[ng][2]};
                    uint32_t b1[2] = {b[ng][1], b[ng][3]};
                    mma16816(acc[mt][ng * 2 + 0], a[mt], b0);
                    mma16816(acc[mt][ng * 2 + 1], a[mt], b1);
                }
        }
    }
}

__global__ __launch_bounds__(256, 2) void qkv_gemm(
    const float* __restrict__ bq, const float* __restrict__ bk, const float* __restrict__ bv)
{
    extern __shared__ __align__(128) char smem[];
    uint32_t sb = smem_u32(smem);
    const int z = blockIdx.z;
    const int m0 = blockIdx.y * 128, n0 = blockIdx.x * 128;
    float acc[2][8][4] = {};
    gemm_main(sb, g_xp + (size_t)m0 * KP, g_wp[z] + (size_t)n0 * KP, acc);

    const float* bias = (z == 0) ? bq : (z == 1) ? bk : bv;
    const int lane = threadIdx.x & 31, wid = threadIdx.x >> 5;
    const int wm = (wid & 3) * 32, wn = (wid >> 2) * 64;
    const int row_l = lane >> 2, col_l = (lane & 3) * 2;
    const int h = (n0 + wn) >> 6;

    if (z <= 1) {
        __nv_bfloat16* dstp = (z == 0) ? g_qp : g_kp;
#pragma unroll
        for (int mt = 0; mt < 2; mt++) {
            int mr = m0 + wm + mt * 16 + row_l;
            int bb = mr >> 11, t = mr & (T_ - 1);
            uint32_t* r0p = reinterpret_cast<uint32_t*>(dstp + ((size_t)(bb*NH_+h)*T_ + t) * KPH);
            uint32_t* r8p = r0p + 8 * (KPH / 2);
#pragma unroll
            for (int nt = 0; nt < 8; nt++) {
                int c = nt * 8 + col_l;
                float bx = bias[n0+wn+c], by = bias[n0+wn+c+1];
                float v0x = acc[mt][nt][0]+bx, v0y = acc[mt][nt][1]+by;
                float v1x = acc[mt][nt][2]+bx, v1y = acc[mt][nt][3]+by;
                int ci = nt * 4 + (lane & 3);
                r0p[ci] = bfpair(v0x, v0y); r0p[32+ci] = bfpair(bflo(v0x), bflo(v0y));
                r8p[ci] = bfpair(v1x, v1y); r8p[32+ci] = bfpair(bflo(v1x), bflo(v1y));
            }
        }
    } else {
#pragma unroll
        for (int mt = 0; mt < 2; mt++) {
            int mr = m0 + wm + mt * 16 + row_l;
            int bb = mr >> 11, t = mr & (T_ - 1);
            float* r0p = g_v + ((size_t)(bb*NH_+h)*T_ + t) * HD_;
            float* r8p = r0p + 8 * HD_;
#pragma unroll
            for (int nt = 0; nt < 8; nt++) {
                int c = nt * 8 + col_l;
                float2 bi = *reinterpret_cast<const float2*>(&bias[n0+wn+c]);
                float2 v0 = {acc[mt][nt][0]+bi.x, acc[mt][nt][1]+bi.y};
                float2 v1 = {acc[mt][nt][2]+bi.x, acc[mt][nt][3]+bi.y};
                *reinterpret_cast<float2*>(r0p + c) = v0;
                *reinterpret_cast<float2*>(r8p + c) = v1;
            }
        }
    }
}

__global__ __launch_bounds__(256, 2) void proj_gemm(const float* __restrict__ bp, float* __restrict__ outC)
{
    extern __shared__ __align__(128) char smem[];
    uint32_t sb = smem_u32(smem);
    const int m0 = blockIdx.y * 128, n0 = blockIdx.x * 128;
    float acc[2][8][4] = {};
    gemm_main(sb, g_ap + (size_t)m0 * KP, g_wp[3] + (size_t)n0 * KP, acc);
    const int lane = threadIdx.x & 31, wid = threadIdx.x >> 5;
    const int wm = (wid & 3) * 32, wn = (wid >> 2) * 64;
    const int row_l = lane >> 2, col_l = (lane & 3) * 2;
#pragma unroll
    for (int mt = 0; mt < 2; mt++) {
        int m = m0 + wm + mt * 16 + row_l;
        float* r0p = outC + (size_t)m * D_;
        float* r8p = r0p + 8 * D_;
#pragma unroll
        for (int nt = 0; nt < 8; nt++) {
            int n = n0 + wn + nt * 8 + col_l;
            float2 bi = *reinterpret_cast<const float2*>(&bp[n]);
            float2 v0 = {acc[mt][nt][0]+bi.x, acc[mt][nt][1]+bi.y};
            float2 v1 = {acc[mt][nt][2]+bi.x, acc[mt][nt][3]+bi.y};
            *reinterpret_cast<float2*>(r0p + n) = v0;
            *reinterpret_cast<float2*>(r8p + n) = v1;
        }
    }
}

// ---------------- HMMA flash (dedup [h|l] operands, register frag reuse) ----------------
#define FQS 0
#define FKV 32768           // K buf: +buf*32768 ; V at +16384
#define FPS2 32768          // merge O dump (reuses KV buf0, dead after loop)
#define FML 65536           // merge m/l (reuses KV buf1)
#define FLASH_SMEM 98304

__device__ __forceinline__ uint32_t off256(int r, int g) {
    return (uint32_t)(r * 256 + ((g ^ (r & 7)) << 4));
}
__device__ __forceinline__ void f_kv(uint32_t sb, const char* gk, const char* gv, int jt, int buf)
{
    const int tid = threadIdx.x;
    uint32_t ks = sb + FKV + buf * 32768;
    uint32_t vs = ks + 16384;
#pragma unroll
    for (int i = 0; i < 4; i++) {
        int ch = tid + i * 256;          // 0..1023
        int r = ch >> 4, gr = ch & 15;
        cp_async16(ks + off256(r, gr), gk + ((size_t)(jt*64 + r)*KPH + gr*8) * 2);
    }
#pragma unroll
    for (int i = 0; i < 4; i++) {
        int ch = tid + i * 256;
        int r = ch >> 4, gr = ch & 15;   // r = head dim c
        cp_async16(vs + off256(r, gr), gv + ((size_t)r*2*T_ + jt*128 + gr*8) * 2);
    }
}

__global__ void __launch_bounds__(256, 1) flash_mma()
{
    extern __shared__ __align__(128) char sm[];
    uint32_t sb = smem_u32(sm);
    const int qt = (T_/128 - 1) - blockIdx.x;
    const int bh = blockIdx.y;
    const int tid = threadIdx.x, lane = tid & 31, w = tid >> 5;
    const int wm = (w & 3) * 32, g = w >> 2;
    const int rowq = lane >> 2, colq = (lane & 3) * 2;
    const int rA = wm + (lane & 15), kgl = (lane >> 4) & 1;

    const char* gq = (const char*)(g_qp + ((size_t)bh*T_ + (size_t)qt*128) * KPH);
    const char* gk = (const char*)(g_kp + (size_t)bh*T_*KPH);
    const char* gv = (const char*)(g_vp + (size_t)bh*HD_*2*T_);

#pragma unroll
    for (int i = 0; i < 8; i++) {
        int ch = tid + i * 256;          // 0..2047
        int r = ch >> 4, gr = ch & 15;
        cp_async16(sb + FQS + off256(r, gr), gq + ((size_t)r*KPH + gr*8) * 2);
    }
    f_kv(sb, gk, gv, 0, 0);
    CP_COMMIT();

    float O[2][8][4] = {};
    float mr[2][2] = {{-1e30f,-1e30f},{-1e30f,-1e30f}};
    float lr[2][2] = {{0.f,0.f},{0.f,0.f}};

    const int njt = 2 * qt + 2;
    for (int jt = 0; jt < njt; jt++) {
        const int buf = jt & 1;
        CP_WAIT0();
        __syncthreads();
        if (jt + 1 < njt) { f_kv(sb, gk, gv, jt + 1, buf ^ 1); CP_COMMIT(); }

        const bool skip_all = (jt == 2 * qt + 1) && (wm < 64);
        if (skip_all) continue;

        // ---- S = QK^T via explicit 3-term: Qh·Kh + Ql·Kh + Qh·Kl ----
        float s[2][4][4] = {};
        {
            uint32_t kS = sb + FKV + buf * 32768;
            const int rB = g * 32 + (lane & 15);
#pragma unroll
            for (int j = 0; j < 4; j++) {
                const int grh = 2 * j + kgl, grl = 8 + 2 * j + kgl;
                uint32_t aH[2][4], aL[2][4], bH[2][4], bL[2][4];
                ldsm4(sb + FQS + off256(rA, grh), aH[0]);
                ldsm4(sb + FQS + off256(rA + 16, grh), aH[1]);
                ldsm4(kS + off256(rB, grh), bH[0]);
                ldsm4(kS + off256(rB + 16, grh), bH[1]);
#pragma unroll
                for (int mt = 0; mt < 2; mt++)
#pragma unroll
                    for (int kk = 0; kk < 2; kk++) {
                        uint32_t p0[2] = {bH[kk][0], bH[kk][2]};
                        uint32_t p1[2] = {bH[kk][1], bH[kk][3]};
                        mma16816(s[mt][kk*2+0], aH[mt], p0);
                        mma16816(s[mt][kk*2+1], aH[mt], p1);
                    }
                ldsm4(sb + FQS + off256(rA, grl), aL[0]);
                ldsm4(sb + FQS + off256(rA + 16, grl), aL[1]);
#pragma unroll
                for (int mt = 0; mt < 2; mt++)
#pragma unroll
                    for (int kk = 0; kk < 2; kk++) {
                        uint32_t p0[2] = {bH[kk][0], bH[kk][2]};
                        uint32_t p1[2] = {bH[kk][1], bH[kk][3]};
                        mma16816(s[mt][kk*2+0], aL[mt], p0);
                        mma16816(s[mt][kk*2+1], aL[mt], p1);
                    }
                ldsm4(kS + off256(rB, grl), bL[0]);
                ldsm4(kS + off256(rB + 16, grl), bL[1]);
#pragma unroll
                for (int mt = 0; mt < 2; mt++)
#pragma unroll
                    for (int kk = 0; kk < 2; kk++) {
                        uint32_t p0[2] = {bL[kk][0], bL[kk][2]};
                        uint32_t p1[2] = {bL[kk][1], bL[kk][3]};
                        mma16816(s[mt][kk*2+0], aH[mt], p0);
                        mma16816(s[mt][kk*2+1], aH[mt], p1);
                    }
            }
        }
        // causal mask only where the diagonal crosses this warp tile
        if ((jt == 2 * qt && wm < 64) || (jt == 2 * qt + 1 && wm >= 64)) {
            const int rg0 = qt * 128 + wm + rowq;
            const int cg0 = jt * 64 + g * 32 + colq;
#pragma unroll
            for (int mt = 0; mt < 2; mt++)
#pragma unroll
                for (int nt = 0; nt < 4; nt++)
#pragma unroll
                    for (int e = 0; e < 4; e++)
                        if (cg0 + nt * 8 + (e & 1) > rg0 + mt * 16 + (e >> 1) * 8)
                            s[mt][nt][e] = -1e30f;
        }
        // ---- online softmax per (mt, row-group) ----
        float psc[2][2];
#pragma unroll
        for (int mt = 0; mt < 2; mt++)
#pragma unroll
            for (int rg = 0; rg < 2; rg++) {
                float tm = -1e30f;
#pragma unroll
                for (int nt = 0; nt < 4; nt++)
                    tm = fmaxf(tm, fmaxf(s[mt][nt][rg*2], s[mt][nt][rg*2+1]));
                tm = fmaxf(tm, __shfl_xor_sync(0xffffffffu, tm, 1));
                tm = fmaxf(tm, __shfl_xor_sync(0xffffffffu, tm, 2));
                float mn = fmaxf(mr[mt][rg], tm);
                float sc = __expf(mr[mt][rg] - mn);
                float rs = 0.0f;
#pragma unroll
                for (int nt = 0; nt < 4; nt++) {
                    float p0 = __expf(s[mt][nt][rg*2] - mn);
                    float p1 = __expf(s[mt][nt][rg*2+1] - mn);
                    s[mt][nt][rg*2] = p0; s[mt][nt][rg*2+1] = p1;
                    rs += p0 + p1;
                }
                rs += __shfl_xor_sync(0xffffffffu, rs, 1);
                rs += __shfl_xor_sync(0xffffffffu, rs, 2);
                lr[mt][rg] = lr[mt][rg] * sc + rs;
                mr[mt][rg] = mn;
                psc[mt][rg] = sc;
            }
#pragma unroll
        for (int mt = 0; mt < 2; mt++)
#pragma unroll
            for (int ot = 0; ot < 8; ot++) {
                O[mt][ot][0] *= psc[mt][0]; O[mt][ot][1] *= psc[mt][0];
                O[mt][ot][2] *= psc[mt][1]; O[mt][ot][3] *= psc[mt][1];
            }
        // ---- P fragments in registers (acc layout == A layout) ----
        uint32_t hiA[2][2][4], loA[2][2][4];
#pragma unroll
        for (int mt = 0; mt < 2; mt++)
#pragma unroll
            for (int j2 = 0; j2 < 2; j2++) {
                const float* s0 = s[mt][2*j2];
                const float* s1 = s[mt][2*j2+1];
                hiA[mt][j2][0] = bfpair(s0[0], s0[1]);
                hiA[mt][j2][1] = bfpair(s0[2], s0[3]);
                hiA[mt][j2][2] = bfpair(s1[0], s1[1]);
                hiA[mt][j2][3] = bfpair(s1[2], s1[3]);
                loA[mt][j2][0] = bfpair(bflo(s0[0]), bflo(s0[1]));
                loA[mt][j2][1] = bfpair(bflo(s0[2]), bflo(s0[3]));
                loA[mt][j2][2] = bfpair(bflo(s1[0]), bflo(s1[1]));
                loA[mt][j2][3] = bfpair(bflo(s1[2]), bflo(s1[3]));
            }
        // ---- O += P·V via explicit 3-term: Ph·Vh + Ph·Vl + Pl·Vh ----
        {
            uint32_t vS = sb + FKV + buf * 32768 + 16384;
            const int rV = lane & 15;
#pragma unroll
            for (int jj = 0; jj < 2; jj++) {
                const int grh = 8 * g + 2 * jj + kgl;
                const int grl = grh + 4;
                uint32_t bh4[4][4], bl4[4][4];
#pragma unroll
                for (int ng = 0; ng < 4; ng++) ldsm4(vS + off256(rV + 16*ng, grh), bh4[ng]);
#pragma unroll
                for (int mt = 0; mt < 2; mt++)
#pragma unroll
                    for (int ng = 0; ng < 4; ng++) {
                        uint32_t p0[2] = {bh4[ng][0], bh4[ng][2]};
                        uint32_t p1[2] = {bh4[ng][1], bh4[ng][3]};
                        mma16816(O[mt][ng*2+0], hiA[mt][jj], p0);
                        mma16816(O[mt][ng*2+1], hiA[mt][jj], p1);
                    }
#pragma unroll
                for (int ng = 0; ng < 4; ng++) ldsm4(vS + off256(rV + 16*ng, grl), bl4[ng]);
#pragma unroll
                for (int mt = 0; mt < 2; mt++)
#pragma unroll
                    for (int ng = 0; ng < 4; ng++) {
                        uint32_t p0[2] = {bl4[ng][0], bl4[ng][2]};
                        uint32_t p1[2] = {bl4[ng][1], bl4[ng][3]};
                        mma16816(O[mt][ng*2+0], hiA[mt][jj], p0);
                        mma16816(O[mt][ng*2+1], hiA[mt][jj], p1);
                    }
#pragma unroll
                for (int mt = 0; mt < 2; mt++)
#pragma unroll
                    for (int ng = 0; ng < 4; ng++) {
                        uint32_t p0[2] = {bh4[ng][0], bh4[ng][2]};
                        uint32_t p1[2] = {bh4[ng][1], bh4[ng][3]};
                        mma16816(O[mt][ng*2+0], loA[mt][jj], p0);
                        mma16816(O[mt][ng*2+1], loA[mt][jj], p1);
                    }
            }
        }
    }
    // ---- merge halves (reuses dead KV smem) ----
    __syncthreads();
    if (g == 1) {
#pragma unroll
        for (int mt = 0; mt < 2; mt++)
#pragma unroll
            for (int rg = 0; rg < 2; rg++) {
                int r = wm + mt * 16 + rowq + rg * 8;
                if ((lane & 3) == 0)
                    *reinterpret_cast<float2*>(sm + FML + r * 8) = make_float2(mr[mt][rg], lr[mt][rg]);
#pragma unroll
                for (int nt = 0; nt < 8; nt++) {
                    int c = nt * 8 + colq;
                    *reinterpret_cast<float2*>(sm + FPS2 + (r * 64 + c) * 4) =
                        make_float2(O[mt][nt][rg*2], O[mt][nt][rg*2+1]);
                }
            }
    }
    __syncthreads();
    if (g == 0) {
        const int h = bh & 15, bb = bh >> 4;
#pragma unroll
        for (int mt = 0; mt < 2; mt++)
#pragma unroll
            for (int rg = 0; rg < 2; rg++) {
                int rl = wm + mt * 16 + rowq + rg * 8;
                float2 ml1 = *reinterpret_cast<float2*>(sm + FML + rl * 8);
                float M = fmaxf(mr[mt][rg], ml1.x);
                float sc0 = __expf(mr[mt][rg] - M), sc1 = __expf(ml1.x - M);
                float inv = 1.0f / (lr[mt][rg] * sc0 + ml1.y * sc1);
                int t = qt * 128 + rl;
                uint32_t* dst = reinterpret_cast<uint32_t*>(
                    g_ap + ((size_t)bb * T_ + t) * KP + 3 * (h * 64));
#pragma unroll
                for (int nt = 0; nt < 8; nt++) {
                    int c = nt * 8 + colq;
                    float2 o1 = *reinterpret_cast<float2*>(sm + FPS2 + (rl * 64 + c) * 4);
                    float v0 = (O[mt][nt][rg*2] * sc0 + o1.x * sc1) * inv;
                    float v1 = (O[mt][nt][rg*2+1] * sc0 + o1.y * sc1) * inv;
                    uint32_t* d = dst + (3 * c) / 2;
                    d[0] = bfpair(v0, bflo(v0));
                    d[1] = bfpair(v0, v1);
                    d[2] = bfpair(bflo(v1), v1);
                }
            }
    }
}

// ---------------- launch ----------------
extern "C" void kernel_launch(void* const* d_in, const int* in_sizes, int n_in,
                              void* d_out, int out_size)
{
    const float* x  = (const float*)d_in[0];
    const float* Wk = (const float*)d_in[1];
    const float* bk = (const float*)d_in[2];
    const float* Wq = (const float*)d_in[3];
    const float* bq = (const float*)d_in[4];
    const float* Wv = (const float*)d_in[5];
    const float* bv = (const float*)d_in[6];
    const float* Wp = (const float*)d_in[7];
    const float* bp = (const float*)d_in[8];
    float* out = (float*)d_out;

    pack_a_kernel<<<(BT_ * D_) / (4 * 256), 256>>>(x);
    pack_w_kernel<<<dim3(32, 32, 4), 256>>>(Wq, Wk, Wv, Wp);

    cudaFuncSetAttribute(qkv_gemm, cudaFuncAttributeMaxDynamicSharedMemorySize, GSMEM);
    cudaFuncSetAttribute(proj_gemm, cudaFuncAttributeMaxDynamicSharedMemorySize, GSMEM);
    cudaFuncSetAttribute(flash_mma, cudaFuncAttributeMaxDynamicSharedMemorySize, FLASH_SMEM);

    qkv_gemm<<<dim3(8, 64, 3), 256, GSMEM>>>(bq, bk, bv);
    pack_v_kernel<<<dim3(T_ / 64, B_ * NH_), 256>>>();
    flash_mma<<<dim3(T_ / 128, B_ * NH_), 256, FLASH_SMEM>>>();
    proj_gemm<<<dim3(8, 64), 256, GSMEM>>>(bp, out);
}

// round 8
// speedup vs baseline: 1.8021x; 1.0523x over previous
#include <cuda_runtime.h>
#include <cuda_bf16.h>
#include <cstdint>
#include <math.h>

#define B_  4
#define T_  2048
#define D_  1024
#define NH_ 16
#define HD_ 64
#define BT_ (B_*T_)
#define KD  2048     // dedup GEMM contraction: [h(1024)|l(1024)]
#define KPH 128      // flash packed head dim: [h(64)|l(64)]

__device__ __align__(128) __nv_bfloat16 g_xp[(size_t)BT_*KD];
__device__ __align__(128) __nv_bfloat16 g_wp[4][(size_t)D_*KD];
__device__ __align__(128) __nv_bfloat16 g_ap[(size_t)BT_*KD];
__device__ __align__(128) __nv_bfloat16 g_qp[(size_t)B_*NH_*T_*KPH];
__device__ __align__(128) __nv_bfloat16 g_kp[(size_t)B_*NH_*T_*KPH];
__device__ __align__(128) __nv_bfloat16 g_vp[(size_t)B_*NH_*HD_*2*T_];
__device__ float g_v[(size_t)B_*NH_*T_*HD_];

__device__ __forceinline__ uint32_t smem_u32(const void* p) {
    uint32_t a;
    asm("{ .reg .u64 t; cvta.to.shared.u64 t, %1; cvt.u32.u64 %0, t; }" : "=r"(a) : "l"(p));
    return a;
}
__device__ __forceinline__ void cp_async16(uint32_t s, const void* g) {
    asm volatile("cp.async.cg.shared.global [%0], [%1], 16;" :: "r"(s), "l"(g));
}
#define CP_COMMIT() asm volatile("cp.async.commit_group;" ::: "memory")
#define CP_WAIT1()  asm volatile("cp.async.wait_group 1;" ::: "memory")
#define CP_WAIT0()  asm volatile("cp.async.wait_group 0;" ::: "memory")
__device__ __forceinline__ void ldsm4(uint32_t addr, uint32_t r[4]) {
    asm volatile("ldmatrix.sync.aligned.m8n8.x4.shared.b16 {%0,%1,%2,%3}, [%4];"
                 : "=r"(r[0]), "=r"(r[1]), "=r"(r[2]), "=r"(r[3]) : "r"(addr));
}
__device__ __forceinline__ void mma16816(float d[4], const uint32_t a[4], const uint32_t b[2]) {
    asm volatile("mma.sync.aligned.m16n8k16.row.col.f32.bf16.bf16.f32 "
                 "{%0,%1,%2,%3}, {%4,%5,%6,%7}, {%8,%9}, {%0,%1,%2,%3};"
                 : "+f"(d[0]), "+f"(d[1]), "+f"(d[2]), "+f"(d[3])
                 : "r"(a[0]), "r"(a[1]), "r"(a[2]), "r"(a[3]), "r"(b[0]), "r"(b[1]));
}
__device__ __forceinline__ uint32_t bfpair(float x, float y) {
    __nv_bfloat162 t = __floats2bfloat162_rn(x, y);
    return *reinterpret_cast<uint32_t*>(&t);
}
__device__ __forceinline__ float bflo(float x) {
    return x - __bfloat162float(__float2bfloat16(x));
}

// ---------------- pack kernels (dedup [h|l]) ----------------
__global__ __launch_bounds__(256) void pack_a_kernel(const float* __restrict__ X)
{
    int idx = blockIdx.x * 256 + threadIdx.x;
    size_t e = (size_t)idx * 4;
    float4 v = reinterpret_cast<const float4*>(X)[idx];
    int m = (int)(e >> 10), k = (int)(e & 1023);
    uint32_t* dst = reinterpret_cast<uint32_t*>(g_xp + (size_t)m * KD);
    dst[(k >> 1) + 0] = bfpair(v.x, v.y);
    dst[(k >> 1) + 1] = bfpair(v.z, v.w);
    dst[((1024 + k) >> 1) + 0] = bfpair(bflo(v.x), bflo(v.y));
    dst[((1024 + k) >> 1) + 1] = bfpair(bflo(v.z), bflo(v.w));
}

__global__ __launch_bounds__(256) void pack_w_kernel(
    const float* __restrict__ Wq, const float* __restrict__ Wk,
    const float* __restrict__ Wv, const float* __restrict__ Wp)
{
    const float* W = (blockIdx.z == 0) ? Wq : (blockIdx.z == 1) ? Wk :
                     (blockIdx.z == 2) ? Wv : Wp;
    __nv_bfloat16* out = g_wp[blockIdx.z];
    __shared__ float tile[32][33];
    const int tid = threadIdx.x;
    const int n0 = blockIdx.x * 32, k0 = blockIdx.y * 32;
#pragma unroll
    for (int i = 0; i < 4; i++) {
        int kk = (tid >> 5) + i * 8;
        tile[kk][tid & 31] = W[(size_t)(k0 + kk) * D_ + n0 + (tid & 31)];
    }
    __syncthreads();
#pragma unroll
    for (int i = 0; i < 4; i++) {
        int nn = (tid >> 5) + i * 8, kl = tid & 31;
        float v = tile[kl][nn];
        __nv_bfloat16 hi = __float2bfloat16(v);
        size_t base = (size_t)(n0 + nn) * KD + (k0 + kl);
        out[base] = hi;
        out[base + 1024] = __float2bfloat16(v - __bfloat162float(hi));
    }
}

// V transpose-pack: g_v[bh][s][c] -> g_vp[bh][c][jt*128 + grp*64 + (Vh32|Vl32)]
__global__ __launch_bounds__(256) void pack_v_kernel()
{
    __shared__ float tile[64][65];
    const int tl = blockIdx.x, bh = blockIdx.y;
    const float* src = g_v + ((size_t)bh * T_ + tl * 64) * HD_;
    const int tid = threadIdx.x;
#pragma unroll
    for (int i = 0; i < 16; i++) {
        int idx = tid + i * 256;
        tile[idx >> 6][idx & 63] = src[(idx >> 6) * HD_ + (idx & 63)];
    }
    __syncthreads();
    __nv_bfloat16* dstb = g_vp + (size_t)bh * HD_ * 2 * T_ + (size_t)tl * 128;
#pragma unroll
    for (int i = 0; i < 16; i++) {
        int idx = tid + i * 256;
        int c = idx >> 6, s = idx & 63;
        int grp = s >> 5, sl = s & 31;
        float v = tile[s][c];
        __nv_bfloat16 hi = __float2bfloat16(v);
        __nv_bfloat16* dr = dstb + (size_t)c * 2 * T_ + grp * 64;
        dr[sl] = hi; dr[32+sl] = __float2bfloat16(v - __bfloat162float(hi));
    }
}

// ---------------- dedup HMMA GEMM (128x128, 32 real k per iter, 3 stages) ----------------
// Stage 32KB: Ah@0, Al@8K, Bh@16K, Bl@24K ; each region 128 rows x 64B, granule swizzle
#define DSTAGE 32768
#define DSMEM (3 * DSTAGE)
#define DNIT (D_ / 32)     // 32

__device__ __forceinline__ uint32_t sw_off(int r, int g) {
    return (uint32_t)(r * 64 + ((g ^ ((r >> 1) & 3)) << 4));
}
__device__ __forceinline__ void load_stage2(uint32_t sbuf,
                                            const __nv_bfloat16* __restrict__ A,
                                            const __nv_bfloat16* __restrict__ B, int k)
{
    const int tid = threadIdx.x;
#pragma unroll
    for (int i = 0; i < 8; i++) {
        int ch = tid + i * 256;          // 0..2047
        int reg = ch >> 9;               // 0=Ah 1=Al 2=Bh 3=Bl
        int r = (ch & 511) >> 2, gc = ch & 3;
        const __nv_bfloat16* base = (reg & 2) ? B : A;
        int off = (reg & 1) ? 1024 : 0;
        cp_async16(sbuf + reg * 8192 + sw_off(r, gc),
                   base + (size_t)r * KD + off + k + gc * 8);
    }
}
__device__ __forceinline__ void gemm_main2(uint32_t smem,
                                           const __nv_bfloat16* __restrict__ A,
                                           const __nv_bfloat16* __restrict__ B,
                                           float acc[2][8][4])
{
    const int tid = threadIdx.x, lane = tid & 31, wid = tid >> 5;
    const int wm = (wid & 3) * 32, wn = (wid >> 2) * 64;
    for (int s = 0; s < 2; s++) { load_stage2(smem + s * DSTAGE, A, B, s * 32); CP_COMMIT(); }
    const int rA = wm + (lane & 15), rB = wn + (lane & 15), kgl = (lane >> 4) & 1;
    int st3 = 0, ld3 = 2;
    for (int ks = 0; ks < DNIT; ks++) {
        CP_WAIT1();
        __syncthreads();
        if (ks + 2 < DNIT) load_stage2(smem + ld3 * DSTAGE, A, B, (ks + 2) * 32);
        CP_COMMIT();
        uint32_t stb = smem + st3 * DSTAGE;
#pragma unroll
        for (int kh = 0; kh < 2; kh++) {
            const int kg = kh * 2 + kgl;
            uint32_t aH[2][4], aL[2][4], bH[4][4], bL[4][4];
#pragma unroll
            for (int mt = 0; mt < 2; mt++) ldsm4(stb + sw_off(rA + mt * 16, kg), aH[mt]);
#pragma unroll
            for (int ng = 0; ng < 4; ng++) ldsm4(stb + 16384 + sw_off(rB + ng * 16, kg), bH[ng]);
#pragma unroll
            for (int mt = 0; mt < 2; mt++)
#pragma unroll
                for (int ng = 0; ng < 4; ng++) {
                    uint32_t b0[2] = {bH[ng][0], bH[ng][2]};
                    uint32_t b1[2] = {bH[ng][1], bH[ng][3]};
                    mma16816(acc[mt][ng * 2 + 0], aH[mt], b0);
                    mma16816(acc[mt][ng * 2 + 1], aH[mt], b1);
                }
#pragma unroll
            for (int mt = 0; mt < 2; mt++) ldsm4(stb + 8192 + sw_off(rA + mt * 16, kg), aL[mt]);
#pragma unroll
            for (int mt = 0; mt < 2; mt++)
#pragma unroll
                for (int ng = 0; ng < 4; ng++) {
                    uint32_t b0[2] = {bH[ng][0], bH[ng][2]};
                    uint32_t b1[2] = {bH[ng][1], bH[ng][3]};
                    mma16816(acc[mt][ng * 2 + 0], aL[mt], b0);
                    mma16816(acc[mt][ng * 2 + 1], aL[mt], b1);
                }
#pragma unroll
            for (int ng = 0; ng < 4; ng++) ldsm4(stb + 24576 + sw_off(rB + ng * 16, kg), bL[ng]);
#pragma unroll
            for (int mt = 0; mt < 2; mt++)
#pragma unroll
                for (int ng = 0; ng < 4; ng++) {
                    uint32_t b0[2] = {bL[ng][0], bL[ng][2]};
                    uint32_t b1[2] = {bL[ng][1], bL[ng][3]};
                    mma16816(acc[mt][ng * 2 + 0], aH[mt], b0);
                    mma16816(acc[mt][ng * 2 + 1], aH[mt], b1);
                }
        }
        st3 = (st3 == 2) ? 0 : st3 + 1;
        ld3 = (ld3 == 2) ? 0 : ld3 + 1;
    }
}

__global__ __launch_bounds__(256, 2) void qkv_gemm(
    const float* __restrict__ bq, const float* __restrict__ bk, const float* __restrict__ bv)
{
    extern __shared__ __align__(128) char smem[];
    uint32_t sb = smem_u32(smem);
    const int z = blockIdx.z;
    const int m0 = blockIdx.y * 128, n0 = blockIdx.x * 128;
    float acc[2][8][4] = {};
    gemm_main2(sb, g_xp + (size_t)m0 * KD, g_wp[z] + (size_t)n0 * KD, acc);

    const float* bias = (z == 0) ? bq : (z == 1) ? bk : bv;
    const int lane = threadIdx.x & 31, wid = threadIdx.x >> 5;
    const int wm = (wid & 3) * 32, wn = (wid >> 2) * 64;
    const int row_l = lane >> 2, col_l = (lane & 3) * 2;
    const int h = (n0 + wn) >> 6;

    if (z <= 1) {
        __nv_bfloat16* dstp = (z == 0) ? g_qp : g_kp;
#pragma unroll
        for (int mt = 0; mt < 2; mt++) {
            int mr = m0 + wm + mt * 16 + row_l;
            int bb = mr >> 11, t = mr & (T_ - 1);
            uint32_t* r0p = reinterpret_cast<uint32_t*>(dstp + ((size_t)(bb*NH_+h)*T_ + t) * KPH);
            uint32_t* r8p = r0p + 8 * (KPH / 2);
#pragma unroll
            for (int nt = 0; nt < 8; nt++) {
                int c = nt * 8 + col_l;
                float bx = bias[n0+wn+c], by = bias[n0+wn+c+1];
                float v0x = acc[mt][nt][0]+bx, v0y = acc[mt][nt][1]+by;
                float v1x = acc[mt][nt][2]+bx, v1y = acc[mt][nt][3]+by;
                int ci = nt * 4 + (lane & 3);
                r0p[ci] = bfpair(v0x, v0y); r0p[32+ci] = bfpair(bflo(v0x), bflo(v0y));
                r8p[ci] = bfpair(v1x, v1y); r8p[32+ci] = bfpair(bflo(v1x), bflo(v1y));
            }
        }
    } else {
#pragma unroll
        for (int mt = 0; mt < 2; mt++) {
            int mr = m0 + wm + mt * 16 + row_l;
            int bb = mr >> 11, t = mr & (T_ - 1);
            float* r0p = g_v + ((size_t)(bb*NH_+h)*T_ + t) * HD_;
            float* r8p = r0p + 8 * HD_;
#pragma unroll
            for (int nt = 0; nt < 8; nt++) {
                int c = nt * 8 + col_l;
                float2 bi = *reinterpret_cast<const float2*>(&bias[n0+wn+c]);
                float2 v0 = {acc[mt][nt][0]+bi.x, acc[mt][nt][1]+bi.y};
                float2 v1 = {acc[mt][nt][2]+bi.x, acc[mt][nt][3]+bi.y};
                *reinterpret_cast<float2*>(r0p + c) = v0;
                *reinterpret_cast<float2*>(r8p + c) = v1;
            }
        }
    }
}

__global__ __launch_bounds__(256, 2) void proj_gemm(const float* __restrict__ bp, float* __restrict__ outC)
{
    extern __shared__ __align__(128) char smem[];
    uint32_t sb = smem_u32(smem);
    const int m0 = blockIdx.y * 128, n0 = blockIdx.x * 128;
    float acc[2][8][4] = {};
    gemm_main2(sb, g_ap + (size_t)m0 * KD, g_wp[3] + (size_t)n0 * KD, acc);
    const int lane = threadIdx.x & 31, wid = threadIdx.x >> 5;
    const int wm = (wid & 3) * 32, wn = (wid >> 2) * 64;
    const int row_l = lane >> 2, col_l = (lane & 3) * 2;
#pragma unroll
    for (int mt = 0; mt < 2; mt++) {
        int m = m0 + wm + mt * 16 + row_l;
        float* r0p = outC + (size_t)m * D_;
        float* r8p = r0p + 8 * D_;
#pragma unroll
        for (int nt = 0; nt < 8; nt++) {
            int n = n0 + wn + nt * 8 + col_l;
            float2 bi = *reinterpret_cast<const float2*>(&bp[n]);
            float2 v0 = {acc[mt][nt][0]+bi.x, acc[mt][nt][1]+bi.y};
            float2 v1 = {acc[mt][nt][2]+bi.x, acc[mt][nt][3]+bi.y};
            *reinterpret_cast<float2*>(r0p + n) = v0;
            *reinterpret_cast<float2*>(r8p + n) = v1;
        }
    }
}

// ---------------- HMMA flash (dedup, register frag reuse) ----------------
#define FQS 0
#define FKV 32768
#define FPS2 32768
#define FML 65536
#define FLASH_SMEM 98304

__device__ __forceinline__ uint32_t off256(int r, int g) {
    return (uint32_t)(r * 256 + ((g ^ (r & 7)) << 4));
}
__device__ __forceinline__ void f_kv(uint32_t sb, const char* gk, const char* gv, int jt, int buf)
{
    const int tid = threadIdx.x;
    uint32_t ks = sb + FKV + buf * 32768;
    uint32_t vs = ks + 16384;
#pragma unroll
    for (int i = 0; i < 4; i++) {
        int ch = tid + i * 256;
        int r = ch >> 4, gr = ch & 15;
        cp_async16(ks + off256(r, gr), gk + ((size_t)(jt*64 + r)*KPH + gr*8) * 2);
    }
#pragma unroll
    for (int i = 0; i < 4; i++) {
        int ch = tid + i * 256;
        int r = ch >> 4, gr = ch & 15;
        cp_async16(vs + off256(r, gr), gv + ((size_t)r*2*T_ + jt*128 + gr*8) * 2);
    }
}

__global__ void __launch_bounds__(256, 1) flash_mma()
{
    extern __shared__ __align__(128) char sm[];
    uint32_t sb = smem_u32(sm);
    const int qt = (T_/128 - 1) - blockIdx.x;
    const int bh = blockIdx.y;
    const int tid = threadIdx.x, lane = tid & 31, w = tid >> 5;
    const int wm = (w & 3) * 32, g = w >> 2;
    const int rowq = lane >> 2, colq = (lane & 3) * 2;
    const int rA = wm + (lane & 15), kgl = (lane >> 4) & 1;

    const char* gq = (const char*)(g_qp + ((size_t)bh*T_ + (size_t)qt*128) * KPH);
    const char* gk = (const char*)(g_kp + (size_t)bh*T_*KPH);
    const char* gv = (const char*)(g_vp + (size_t)bh*HD_*2*T_);

#pragma unroll
    for (int i = 0; i < 8; i++) {
        int ch = tid + i * 256;
        int r = ch >> 4, gr = ch & 15;
        cp_async16(sb + FQS + off256(r, gr), gq + ((size_t)r*KPH + gr*8) * 2);
    }
    f_kv(sb, gk, gv, 0, 0);
    CP_COMMIT();

    float O[2][8][4] = {};
    float mr[2][2] = {{-1e30f,-1e30f},{-1e30f,-1e30f}};
    float lr[2][2] = {{0.f,0.f},{0.f,0.f}};

    const int njt = 2 * qt + 2;
    for (int jt = 0; jt < njt; jt++) {
        const int buf = jt & 1;
        CP_WAIT0();
        __syncthreads();
        if (jt + 1 < njt) { f_kv(sb, gk, gv, jt + 1, buf ^ 1); CP_COMMIT(); }

        const bool skip_all = (jt == 2 * qt + 1) && (wm < 64);
        if (skip_all) continue;

        float s[2][4][4] = {};
        {
            uint32_t kS = sb + FKV + buf * 32768;
            const int rB = g * 32 + (lane & 15);
#pragma unroll
            for (int j = 0; j < 4; j++) {
                const int grh = 2 * j + kgl, grl = 8 + 2 * j + kgl;
                uint32_t aH[2][4], aL[2][4], bH[2][4], bL[2][4];
                ldsm4(sb + FQS + off256(rA, grh), aH[0]);
                ldsm4(sb + FQS + off256(rA + 16, grh), aH[1]);
                ldsm4(kS + off256(rB, grh), bH[0]);
                ldsm4(kS + off256(rB + 16, grh), bH[1]);
#pragma unroll
                for (int mt = 0; mt < 2; mt++)
#pragma unroll
                    for (int kk = 0; kk < 2; kk++) {
                        uint32_t p0[2] = {bH[kk][0], bH[kk][2]};
                        uint32_t p1[2] = {bH[kk][1], bH[kk][3]};
                        mma16816(s[mt][kk*2+0], aH[mt], p0);
                        mma16816(s[mt][kk*2+1], aH[mt], p1);
                    }
                ldsm4(sb + FQS + off256(rA, grl), aL[0]);
                ldsm4(sb + FQS + off256(rA + 16, grl), aL[1]);
#pragma unroll
                for (int mt = 0; mt < 2; mt++)
#pragma unroll
                    for (int kk = 0; kk < 2; kk++) {
                        uint32_t p0[2] = {bH[kk][0], bH[kk][2]};
                        uint32_t p1[2] = {bH[kk][1], bH[kk][3]};
                        mma16816(s[mt][kk*2+0], aL[mt], p0);
                        mma16816(s[mt][kk*2+1], aL[mt], p1);
                    }
                ldsm4(kS + off256(rB, grl), bL[0]);
                ldsm4(kS + off256(rB + 16, grl), bL[1]);
#pragma unroll
                for (int mt = 0; mt < 2; mt++)
#pragma unroll
                    for (int kk = 0; kk < 2; kk++) {
                        uint32_t p0[2] = {bL[kk][0], bL[kk][2]};
                        uint32_t p1[2] = {bL[kk][1], bL[kk][3]};
                        mma16816(s[mt][kk*2+0], aH[mt], p0);
                        mma16816(s[mt][kk*2+1], aH[mt], p1);
                    }
            }
        }
        if ((jt == 2 * qt && wm < 64) || (jt == 2 * qt + 1 && wm >= 64)) {
            const int rg0 = qt * 128 + wm + rowq;
            const int cg0 = jt * 64 + g * 32 + colq;
#pragma unroll
            for (int mt = 0; mt < 2; mt++)
#pragma unroll
                for (int nt = 0; nt < 4; nt++)
#pragma unroll
                    for (int e = 0; e < 4; e++)
                        if (cg0 + nt * 8 + (e & 1) > rg0 + mt * 16 + (e >> 1) * 8)
                            s[mt][nt][e] = -1e30f;
        }
        float psc[2][2];
#pragma unroll
        for (int mt = 0; mt < 2; mt++)
#pragma unroll
            for (int rg = 0; rg < 2; rg++) {
                float tm = -1e30f;
#pragma unroll
                for (int nt = 0; nt < 4; nt++)
                    tm = fmaxf(tm, fmaxf(s[mt][nt][rg*2], s[mt][nt][rg*2+1]));
                tm = fmaxf(tm, __shfl_xor_sync(0xffffffffu, tm, 1));
                tm = fmaxf(tm, __shfl_xor_sync(0xffffffffu, tm, 2));
                float mn = fmaxf(mr[mt][rg], tm);
                float sc = __expf(mr[mt][rg] - mn);
                float rs = 0.0f;
#pragma unroll
                for (int nt = 0; nt < 4; nt++) {
                    float p0 = __expf(s[mt][nt][rg*2] - mn);
                    float p1 = __expf(s[mt][nt][rg*2+1] - mn);
                    s[mt][nt][rg*2] = p0; s[mt][nt][rg*2+1] = p1;
                    rs += p0 + p1;
                }
                rs += __shfl_xor_sync(0xffffffffu, rs, 1);
                rs += __shfl_xor_sync(0xffffffffu, rs, 2);
                lr[mt][rg] = lr[mt][rg] * sc + rs;
                mr[mt][rg] = mn;
                psc[mt][rg] = sc;
            }
#pragma unroll
        for (int mt = 0; mt < 2; mt++)
#pragma unroll
            for (int ot = 0; ot < 8; ot++) {
                O[mt][ot][0] *= psc[mt][0]; O[mt][ot][1] *= psc[mt][0];
                O[mt][ot][2] *= psc[mt][1]; O[mt][ot][3] *= psc[mt][1];
            }
        uint32_t hiA[2][2][4], loA[2][2][4];
#pragma unroll
        for (int mt = 0; mt < 2; mt++)
#pragma unroll
            for (int j2 = 0; j2 < 2; j2++) {
                const float* s0 = s[mt][2*j2];
                const float* s1 = s[mt][2*j2+1];
                hiA[mt][j2][0] = bfpair(s0[0], s0[1]);
                hiA[mt][j2][1] = bfpair(s0[2], s0[3]);
                hiA[mt][j2][2] = bfpair(s1[0], s1[1]);
                hiA[mt][j2][3] = bfpair(s1[2], s1[3]);
                loA[mt][j2][0] = bfpair(bflo(s0[0]), bflo(s0[1]));
                loA[mt][j2][1] = bfpair(bflo(s0[2]), bflo(s0[3]));
                loA[mt][j2][2] = bfpair(bflo(s1[0]), bflo(s1[1]));
                loA[mt][j2][3] = bfpair(bflo(s1[2]), bflo(s1[3]));
            }
        {
            uint32_t vS = sb + FKV + buf * 32768 + 16384;
            const int rV = lane & 15;
#pragma unroll
            for (int jj = 0; jj < 2; jj++) {
                const int grh = 8 * g + 2 * jj + kgl;
                const int grl = grh + 4;
                uint32_t bh4[4][4], bl4[4][4];
#pragma unroll
                for (int ng = 0; ng < 4; ng++) ldsm4(vS + off256(rV + 16*ng, grh), bh4[ng]);
#pragma unroll
                for (int mt = 0; mt < 2; mt++)
#pragma unroll
                    for (int ng = 0; ng < 4; ng++) {
                        uint32_t p0[2] = {bh4[ng][0], bh4[ng][2]};
                        uint32_t p1[2] = {bh4[ng][1], bh4[ng][3]};
                        mma16816(O[mt][ng*2+0], hiA[mt][jj], p0);
                        mma16816(O[mt][ng*2+1], hiA[mt][jj], p1);
                    }
#pragma unroll
                for (int ng = 0; ng < 4; ng++) ldsm4(vS + off256(rV + 16*ng, grl), bl4[ng]);
#pragma unroll
                for (int mt = 0; mt < 2; mt++)
#pragma unroll
                    for (int ng = 0; ng < 4; ng++) {
                        uint32_t p0[2] = {bl4[ng][0], bl4[ng][2]};
                        uint32_t p1[2] = {bl4[ng][1], bl4[ng][3]};
                        mma16816(O[mt][ng*2+0], hiA[mt][jj], p0);
                        mma16816(O[mt][ng*2+1], hiA[mt][jj], p1);
                    }
#pragma unroll
                for (int mt = 0; mt < 2; mt++)
#pragma unroll
                    for (int ng = 0; ng < 4; ng++) {
                        uint32_t p0[2] = {bh4[ng][0], bh4[ng][2]};
                        uint32_t p1[2] = {bh4[ng][1], bh4[ng][3]};
                        mma16816(O[mt][ng*2+0], loA[mt][jj], p0);
                        mma16816(O[mt][ng*2+1], loA[mt][jj], p1);
                    }
            }
        }
    }
    __syncthreads();
    if (g == 1) {
#pragma unroll
        for (int mt = 0; mt < 2; mt++)
#pragma unroll
            for (int rg = 0; rg < 2; rg++) {
                int r = wm + mt * 16 + rowq + rg * 8;
                if ((lane & 3) == 0)
                    *reinterpret_cast<float2*>(sm + FML + r * 8) = make_float2(mr[mt][rg], lr[mt][rg]);
#pragma unroll
                for (int nt = 0; nt < 8; nt++) {
                    int c = nt * 8 + colq;
                    *reinterpret_cast<float2*>(sm + FPS2 + (r * 64 + c) * 4) =
                        make_float2(O[mt][nt][rg*2], O[mt][nt][rg*2+1]);
                }
            }
    }
    __syncthreads();
    if (g == 0) {
        const int h = bh & 15, bb = bh >> 4;
#pragma unroll
        for (int mt = 0; mt < 2; mt++)
#pragma unroll
            for (int rg = 0; rg < 2; rg++) {
                int rl = wm + mt * 16 + rowq + rg * 8;
                float2 ml1 = *reinterpret_cast<float2*>(sm + FML + rl * 8);
                float M = fmaxf(mr[mt][rg], ml1.x);
                float sc0 = __expf(mr[mt][rg] - M), sc1 = __expf(ml1.x - M);
                float inv = 1.0f / (lr[mt][rg] * sc0 + ml1.y * sc1);
                int t = qt * 128 + rl;
                uint32_t* dst = reinterpret_cast<uint32_t*>(
                    g_ap + ((size_t)bb * T_ + t) * KD);
#pragma unroll
                for (int nt = 0; nt < 8; nt++) {
                    int c = nt * 8 + colq;
                    float2 o1 = *reinterpret_cast<float2*>(sm + FPS2 + (rl * 64 + c) * 4);
                    float v0 = (O[mt][nt][rg*2] * sc0 + o1.x * sc1) * inv;
                    float v1 = (O[mt][nt][rg*2+1] * sc0 + o1.y * sc1) * inv;
                    dst[(h * 64 + c) >> 1] = bfpair(v0, v1);
                    dst[(1024 + h * 64 + c) >> 1] = bfpair(bflo(v0), bflo(v1));
                }
            }
    }
}

// ---------------- launch ----------------
extern "C" void kernel_launch(void* const* d_in, const int* in_sizes, int n_in,
                              void* d_out, int out_size)
{
    const float* x  = (const float*)d_in[0];
    const float* Wk = (const float*)d_in[1];
    const float* bk = (const float*)d_in[2];
    const float* Wq = (const float*)d_in[3];
    const float* bq = (const float*)d_in[4];
    const float* Wv = (const float*)d_in[5];
    const float* bv = (const float*)d_in[6];
    const float* Wp = (const float*)d_in[7];
    const float* bp = (const float*)d_in[8];
    float* out = (float*)d_out;

    pack_a_kernel<<<(BT_ * D_) / (4 * 256), 256>>>(x);
    pack_w_kernel<<<dim3(32, 32, 4), 256>>>(Wq, Wk, Wv, Wp);

    cudaFuncSetAttribute(qkv_gemm, cudaFuncAttributeMaxDynamicSharedMemorySize, DSMEM);
    cudaFuncSetAttribute(proj_gemm, cudaFuncAttributeMaxDynamicSharedMemorySize, DSMEM);
    cudaFuncSetAttribute(flash_mma, cudaFuncAttributeMaxDynamicSharedMemorySize, FLASH_SMEM);

    qkv_gemm<<<dim3(8, 64, 3), 256, DSMEM>>>(bq, bk, bv);
    pack_v_kernel<<<dim3(T_ / 64, B_ * NH_), 256>>>();
    flash_mma<<<dim3(T_ / 128, B_ * NH_), 256, FLASH_SMEM>>>();
    proj_gemm<<<dim3(8, 64), 256, DSMEM>>>(bp, out);
}

// round 9
// speedup vs baseline: 1.8134x; 1.0063x over previous
#include <cuda_runtime.h>
#include <cuda_bf16.h>
#include <cstdint>
#include <math.h>

#define B_  4
#define T_  2048
#define D_  1024
#define NH_ 16
#define HD_ 64
#define BT_ (B_*T_)
#define KD  2048     // dedup GEMM contraction: [h(1024)|l(1024)]
#define KPH 128      // flash packed head dim: [h(64)|l(64)]

__device__ __align__(128) __nv_bfloat16 g_xp[(size_t)BT_*KD];
__device__ __align__(128) __nv_bfloat16 g_wp[4][(size_t)D_*KD];
__device__ __align__(128) __nv_bfloat16 g_ap[(size_t)BT_*KD];
__device__ __align__(128) __nv_bfloat16 g_qp[(size_t)B_*NH_*T_*KPH];
__device__ __align__(128) __nv_bfloat16 g_kp[(size_t)B_*NH_*T_*KPH];
__device__ __align__(128) __nv_bfloat16 g_vp[(size_t)B_*NH_*HD_*2*T_];

__device__ __forceinline__ uint32_t smem_u32(const void* p) {
    uint32_t a;
    asm("{ .reg .u64 t; cvta.to.shared.u64 t, %1; cvt.u32.u64 %0, t; }" : "=r"(a) : "l"(p));
    return a;
}
__device__ __forceinline__ void cp_async16(uint32_t s, const void* g) {
    asm volatile("cp.async.cg.shared.global [%0], [%1], 16;" :: "r"(s), "l"(g));
}
#define CP_COMMIT() asm volatile("cp.async.commit_group;" ::: "memory")
#define CP_WAIT1()  asm volatile("cp.async.wait_group 1;" ::: "memory")
#define CP_WAIT0()  asm volatile("cp.async.wait_group 0;" ::: "memory")
__device__ __forceinline__ void ldsm4(uint32_t addr, uint32_t r[4]) {
    asm volatile("ldmatrix.sync.aligned.m8n8.x4.shared.b16 {%0,%1,%2,%3}, [%4];"
                 : "=r"(r[0]), "=r"(r[1]), "=r"(r[2]), "=r"(r[3]) : "r"(addr));
}
__device__ __forceinline__ void mma16816(float d[4], const uint32_t a[4], const uint32_t b[2]) {
    asm volatile("mma.sync.aligned.m16n8k16.row.col.f32.bf16.bf16.f32 "
                 "{%0,%1,%2,%3}, {%4,%5,%6,%7}, {%8,%9}, {%0,%1,%2,%3};"
                 : "+f"(d[0]), "+f"(d[1]), "+f"(d[2]), "+f"(d[3])
                 : "r"(a[0]), "r"(a[1]), "r"(a[2]), "r"(a[3]), "r"(b[0]), "r"(b[1]));
}
__device__ __forceinline__ uint32_t bfpair(float x, float y) {
    __nv_bfloat162 t = __floats2bfloat162_rn(x, y);
    return *reinterpret_cast<uint32_t*>(&t);
}
__device__ __forceinline__ float bflo(float x) {
    return x - __bfloat162float(__float2bfloat16(x));
}

// ---------------- pack kernels (dedup [h|l]) ----------------
__global__ __launch_bounds__(256) void pack_a_kernel(const float* __restrict__ X)
{
    int idx = blockIdx.x * 256 + threadIdx.x;
    size_t e = (size_t)idx * 4;
    float4 v = reinterpret_cast<const float4*>(X)[idx];
    int m = (int)(e >> 10), k = (int)(e & 1023);
    uint32_t* dst = reinterpret_cast<uint32_t*>(g_xp + (size_t)m * KD);
    dst[(k >> 1) + 0] = bfpair(v.x, v.y);
    dst[(k >> 1) + 1] = bfpair(v.z, v.w);
    dst[((1024 + k) >> 1) + 0] = bfpair(bflo(v.x), bflo(v.y));
    dst[((1024 + k) >> 1) + 1] = bfpair(bflo(v.z), bflo(v.w));
}

__global__ __launch_bounds__(256) void pack_w_kernel(
    const float* __restrict__ Wq, const float* __restrict__ Wk,
    const float* __restrict__ Wv, const float* __restrict__ Wp)
{
    const float* W = (blockIdx.z == 0) ? Wq : (blockIdx.z == 1) ? Wk :
                     (blockIdx.z == 2) ? Wv : Wp;
    __nv_bfloat16* out = g_wp[blockIdx.z];
    __shared__ float tile[32][33];
    const int tid = threadIdx.x;
    const int n0 = blockIdx.x * 32, k0 = blockIdx.y * 32;
#pragma unroll
    for (int i = 0; i < 4; i++) {
        int kk = (tid >> 5) + i * 8;
        tile[kk][tid & 31] = W[(size_t)(k0 + kk) * D_ + n0 + (tid & 31)];
    }
    __syncthreads();
#pragma unroll
    for (int i = 0; i < 4; i++) {
        int nn = (tid >> 5) + i * 8, kl = tid & 31;
        float v = tile[kl][nn];
        __nv_bfloat16 hi = __float2bfloat16(v);
        size_t base = (size_t)(n0 + nn) * KD + (k0 + kl);
        out[base] = hi;
        out[base + 1024] = __float2bfloat16(v - __bfloat162float(hi));
    }
}

// ---------------- dedup HMMA GEMM (128x128, 32 real k per iter, 3 stages) ----------------
// Stage 32KB: Ah@0, Al@8K, Bh@16K, Bl@24K
#define DSTAGE 32768
#define DSMEM (3 * DSTAGE)
#define DNIT (D_ / 32)     // 32

__device__ __forceinline__ uint32_t sw_off(int r, int g) {
    return (uint32_t)(r * 64 + ((g ^ ((r >> 1) & 3)) << 4));
}
__device__ __forceinline__ void load_stage2(uint32_t sbuf,
                                            const __nv_bfloat16* __restrict__ A,
                                            const __nv_bfloat16* __restrict__ B, int k)
{
    const int tid = threadIdx.x;
#pragma unroll
    for (int i = 0; i < 8; i++) {
        int ch = tid + i * 256;          // 0..2047
        int reg = ch >> 9;               // 0=Ah 1=Al 2=Bh 3=Bl
        int r = (ch & 511) >> 2, gc = ch & 3;
        const __nv_bfloat16* base = (reg & 2) ? B : A;
        int off = (reg & 1) ? 1024 : 0;
        cp_async16(sbuf + reg * 8192 + sw_off(r, gc),
                   base + (size_t)r * KD + off + k + gc * 8);
    }
}
__device__ __forceinline__ void mma_blk(float acc[2][8][4], const uint32_t a[2][4],
                                        const uint32_t bp[2][4], int off) {
#pragma unroll
    for (int mt = 0; mt < 2; mt++)
#pragma unroll
        for (int kk = 0; kk < 2; kk++) {
            uint32_t q0[2] = {bp[kk][0], bp[kk][2]};
            uint32_t q1[2] = {bp[kk][1], bp[kk][3]};
            mma16816(acc[mt][off + kk*2 + 0], a[mt], q0);
            mma16816(acc[mt][off + kk*2 + 1], a[mt], q1);
        }
}
__device__ __forceinline__ void gemm_main2(uint32_t smem,
                                           const __nv_bfloat16* __restrict__ A,
                                           const __nv_bfloat16* __restrict__ B,
                                           float acc[2][8][4])
{
    const int tid = threadIdx.x, lane = tid & 31, wid = tid >> 5;
    const int wm = (wid & 3) * 32, wn = (wid >> 2) * 64;
    for (int s = 0; s < 2; s++) { load_stage2(smem + s * DSTAGE, A, B, s * 32); CP_COMMIT(); }
    const int rA = wm + (lane & 15), rB = wn + (lane & 15), kgl = (lane >> 4) & 1;
    int st3 = 0, ld3 = 2;
    for (int ks = 0; ks < DNIT; ks++) {
        CP_WAIT1();
        __syncthreads();
        if (ks + 2 < DNIT) load_stage2(smem + ld3 * DSTAGE, A, B, (ks + 2) * 32);
        CP_COMMIT();
        uint32_t stb = smem + st3 * DSTAGE;
#pragma unroll
        for (int kh = 0; kh < 2; kh++) {
            const int kg = kh * 2 + kgl;
            uint32_t aH[2][4], aL[2][4], bx[2][4], by[2][4];
            ldsm4(stb + sw_off(rA, kg), aH[0]);
            ldsm4(stb + sw_off(rA + 16, kg), aH[1]);
            ldsm4(stb + 16384 + sw_off(rB, kg), bx[0]);        // Bh ng0,1
            ldsm4(stb + 16384 + sw_off(rB + 16, kg), bx[1]);
            mma_blk(acc, aH, bx, 0);
            ldsm4(stb + 16384 + sw_off(rB + 32, kg), by[0]);   // Bh ng2,3
            ldsm4(stb + 16384 + sw_off(rB + 48, kg), by[1]);
            mma_blk(acc, aH, by, 4);
            ldsm4(stb + 8192 + sw_off(rA, kg), aL[0]);
            ldsm4(stb + 8192 + sw_off(rA + 16, kg), aL[1]);
            mma_blk(acc, aL, bx, 0);
            mma_blk(acc, aL, by, 4);
            ldsm4(stb + 24576 + sw_off(rB, kg), bx[0]);        // Bl ng0,1 (reuse regs)
            ldsm4(stb + 24576 + sw_off(rB + 16, kg), bx[1]);
            mma_blk(acc, aH, bx, 0);
            ldsm4(stb + 24576 + sw_off(rB + 32, kg), by[0]);   // Bl ng2,3
            ldsm4(stb + 24576 + sw_off(rB + 48, kg), by[1]);
            mma_blk(acc, aH, by, 4);
        }
        st3 = (st3 == 2) ? 0 : st3 + 1;
        ld3 = (ld3 == 2) ? 0 : ld3 + 1;
    }
}

__global__ __launch_bounds__(256, 2) void qkv_gemm(
    const float* __restrict__ bq, const float* __restrict__ bk, const float* __restrict__ bv)
{
    extern __shared__ __align__(128) char smem[];
    uint32_t sb = smem_u32(smem);
    const int z = blockIdx.z;
    const int m0 = blockIdx.y * 128, n0 = blockIdx.x * 128;
    float acc[2][8][4] = {};
    gemm_main2(sb, g_xp + (size_t)m0 * KD, g_wp[z] + (size_t)n0 * KD, acc);

    const float* bias = (z == 0) ? bq : (z == 1) ? bk : bv;
    const int lane = threadIdx.x & 31, wid = threadIdx.x >> 5;
    const int wm = (wid & 3) * 32, wn = (wid >> 2) * 64;
    const int row_l = lane >> 2, col_l = (lane & 3) * 2;

    if (z <= 1) {
        const int h = (n0 + wn) >> 6;
        __nv_bfloat16* dstp = (z == 0) ? g_qp : g_kp;
#pragma unroll
        for (int mt = 0; mt < 2; mt++) {
            int mr = m0 + wm + mt * 16 + row_l;
            int bb = mr >> 11, t = mr & (T_ - 1);
            uint32_t* r0p = reinterpret_cast<uint32_t*>(dstp + ((size_t)(bb*NH_+h)*T_ + t) * KPH);
            uint32_t* r8p = r0p + 8 * (KPH / 2);
#pragma unroll
            for (int nt = 0; nt < 8; nt++) {
                int c = nt * 8 + col_l;
                float bxs = bias[n0+wn+c], bys = bias[n0+wn+c+1];
                float v0x = acc[mt][nt][0]+bxs, v0y = acc[mt][nt][1]+bys;
                float v1x = acc[mt][nt][2]+bxs, v1y = acc[mt][nt][3]+bys;
                int ci = nt * 4 + (lane & 3);
                r0p[ci] = bfpair(v0x, v0y); r0p[32+ci] = bfpair(bflo(v0x), bflo(v0y));
                r8p[ci] = bfpair(v1x, v1y); r8p[32+ci] = bfpair(bflo(v1x), bflo(v1y));
            }
        }
    } else {
        // fused V transpose-pack: stage fp32 tile in (dead) smem, emit packed g_vp rows
        float* vt = reinterpret_cast<float*>(smem);
        __syncthreads();                    // all warps done reading stage buffers
#pragma unroll
        for (int mt = 0; mt < 2; mt++) {
            int rl = wm + mt * 16 + row_l;
#pragma unroll
            for (int nt = 0; nt < 8; nt++) {
                int cl = wn + nt * 8 + col_l;
                float bxs = bias[n0+cl], bys = bias[n0+cl+1];
                vt[rl * 130 + cl]           = acc[mt][nt][0] + bxs;
                vt[rl * 130 + cl + 1]       = acc[mt][nt][1] + bys;
                vt[(rl + 8) * 130 + cl]     = acc[mt][nt][2] + bxs;
                vt[(rl + 8) * 130 + cl + 1] = acc[mt][nt][3] + bys;
            }
        }
        __syncthreads();
        const int tid = threadIdx.x;
        const int c_loc = tid >> 1, half = tid & 1;
        const int h = (n0 + c_loc) >> 6;
        const int c = c_loc & 63;
        const int bb = m0 >> 11, t0 = m0 & (T_ - 1);
        const int bh = bb * NH_ + h;
        const int tl = (t0 >> 6) + half;
        uint32_t outbuf[64];
#pragma unroll
        for (int grp = 0; grp < 2; grp++)
#pragma unroll
            for (int sl2 = 0; sl2 < 16; sl2++) {
                float v0 = vt[(half*64 + grp*32 + 2*sl2)     * 130 + c_loc];
                float v1 = vt[(half*64 + grp*32 + 2*sl2 + 1) * 130 + c_loc];
                outbuf[grp*32 + sl2]      = bfpair(v0, v1);
                outbuf[grp*32 + 16 + sl2] = bfpair(bflo(v0), bflo(v1));
            }
        uint4* dst = reinterpret_cast<uint4*>(
            g_vp + (size_t)bh * HD_ * 2 * T_ + (size_t)c * 2 * T_ + tl * 128);
#pragma unroll
        for (int q = 0; q < 16; q++) dst[q] = reinterpret_cast<uint4*>(outbuf)[q];
    }
}

__global__ __launch_bounds__(256, 2) void proj_gemm(const float* __restrict__ bp, float* __restrict__ outC)
{
    extern __shared__ __align__(128) char smem[];
    uint32_t sb = smem_u32(smem);
    const int m0 = blockIdx.y * 128, n0 = blockIdx.x * 128;
    float acc[2][8][4] = {};
    gemm_main2(sb, g_ap + (size_t)m0 * KD, g_wp[3] + (size_t)n0 * KD, acc);
    const int lane = threadIdx.x & 31, wid = threadIdx.x >> 5;
    const int wm = (wid & 3) * 32, wn = (wid >> 2) * 64;
    const int row_l = lane >> 2, col_l = (lane & 3) * 2;
#pragma unroll
    for (int mt = 0; mt < 2; mt++) {
        int m = m0 + wm + mt * 16 + row_l;
        float* r0p = outC + (size_t)m * D_;
        float* r8p = r0p + 8 * D_;
#pragma unroll
        for (int nt = 0; nt < 8; nt++) {
            int n = n0 + wn + nt * 8 + col_l;
            float2 bi = *reinterpret_cast<const float2*>(&bp[n]);
            float2 v0 = {acc[mt][nt][0]+bi.x, acc[mt][nt][1]+bi.y};
            float2 v1 = {acc[mt][nt][2]+bi.x, acc[mt][nt][3]+bi.y};
            *reinterpret_cast<float2*>(r0p + n) = v0;
            *reinterpret_cast<float2*>(r8p + n) = v1;
        }
    }
}

// ---------------- HMMA flash (dedup, register frag reuse) ----------------
#define FQS 0
#define FKV 32768
#define FPS2 32768
#define FML 65536
#define FLASH_SMEM 98304

__device__ __forceinline__ uint32_t off256(int r, int g) {
    return (uint32_t)(r * 256 + ((g ^ (r & 7)) << 4));
}
__device__ __forceinline__ void f_kv(uint32_t sb, const char* gk, const char* gv, int jt, int buf)
{
    const int tid = threadIdx.x;
    uint32_t ks = sb + FKV + buf * 32768;
    uint32_t vs = ks + 16384;
#pragma unroll
    for (int i = 0; i < 4; i++) {
        int ch = tid + i * 256;
        int r = ch >> 4, gr = ch & 15;
        cp_async16(ks + off256(r, gr), gk + ((size_t)(jt*64 + r)*KPH + gr*8) * 2);
    }
#pragma unroll
    for (int i = 0; i < 4; i++) {
        int ch = tid + i * 256;
        int r = ch >> 4, gr = ch & 15;
        cp_async16(vs + off256(r, gr), gv + ((size_t)r*2*T_ + jt*128 + gr*8) * 2);
    }
}

__global__ void __launch_bounds__(256, 1) flash_mma()
{
    extern __shared__ __align__(128) char sm[];
    uint32_t sb = smem_u32(sm);
    const int qt = (T_/128 - 1) - blockIdx.x;
    const int bh = blockIdx.y;
    const int tid = threadIdx.x, lane = tid & 31, w = tid >> 5;
    const int wm = (w & 3) * 32, g = w >> 2;
    const int rowq = lane >> 2, colq = (lane & 3) * 2;
    const int rA = wm + (lane & 15), kgl = (lane >> 4) & 1;

    const char* gq = (const char*)(g_qp + ((size_t)bh*T_ + (size_t)qt*128) * KPH);
    const char* gk = (const char*)(g_kp + (size_t)bh*T_*KPH);
    const char* gv = (const char*)(g_vp + (size_t)bh*HD_*2*T_);

#pragma unroll
    for (int i = 0; i < 8; i++) {
        int ch = tid + i * 256;
        int r = ch >> 4, gr = ch & 15;
        cp_async16(sb + FQS + off256(r, gr), gq + ((size_t)r*KPH + gr*8) * 2);
    }
    f_kv(sb, gk, gv, 0, 0);
    CP_COMMIT();

    float O[2][8][4] = {};
    float mr[2][2] = {{-1e30f,-1e30f},{-1e30f,-1e30f}};
    float lr[2][2] = {{0.f,0.f},{0.f,0.f}};

    const int njt = 2 * qt + 2;
    for (int jt = 0; jt < njt; jt++) {
        const int buf = jt & 1;
        CP_WAIT0();
        __syncthreads();
        if (jt + 1 < njt) { f_kv(sb, gk, gv, jt + 1, buf ^ 1); CP_COMMIT(); }

        const bool skip_all = (jt == 2 * qt + 1) && (wm < 64);
        if (skip_all) continue;

        float s[2][4][4] = {};
        {
            uint32_t kS = sb + FKV + buf * 32768;
            const int rB = g * 32 + (lane & 15);
#pragma unroll
            for (int j = 0; j < 4; j++) {
                const int grh = 2 * j + kgl, grl = 8 + 2 * j + kgl;
                uint32_t aH[2][4], aL[2][4], bH[2][4], bL[2][4];
                ldsm4(sb + FQS + off256(rA, grh), aH[0]);
                ldsm4(sb + FQS + off256(rA + 16, grh), aH[1]);
                ldsm4(kS + off256(rB, grh), bH[0]);
                ldsm4(kS + off256(rB + 16, grh), bH[1]);
#pragma unroll
                for (int mt = 0; mt < 2; mt++)
#pragma unroll
                    for (int kk = 0; kk < 2; kk++) {
                        uint32_t p0[2] = {bH[kk][0], bH[kk][2]};
                        uint32_t p1[2] = {bH[kk][1], bH[kk][3]};
                        mma16816(s[mt][kk*2+0], aH[mt], p0);
                        mma16816(s[mt][kk*2+1], aH[mt], p1);
                    }
                ldsm4(sb + FQS + off256(rA, grl), aL[0]);
                ldsm4(sb + FQS + off256(rA + 16, grl), aL[1]);
#pragma unroll
                for (int mt = 0; mt < 2; mt++)
#pragma unroll
                    for (int kk = 0; kk < 2; kk++) {
                        uint32_t p0[2] = {bH[kk][0], bH[kk][2]};
                        uint32_t p1[2] = {bH[kk][1], bH[kk][3]};
                        mma16816(s[mt][kk*2+0], aL[mt], p0);
                        mma16816(s[mt][kk*2+1], aL[mt], p1);
                    }
                ldsm4(kS + off256(rB, grl), bL[0]);
                ldsm4(kS + off256(rB + 16, grl), bL[1]);
#pragma unroll
                for (int mt = 0; mt < 2; mt++)
#pragma unroll
                    for (int kk = 0; kk < 2; kk++) {
                        uint32_t p0[2] = {bL[kk][0], bL[kk][2]};
                        uint32_t p1[2] = {bL[kk][1], bL[kk][3]};
                        mma16816(s[mt][kk*2+0], aH[mt], p0);
                        mma16816(s[mt][kk*2+1], aH[mt], p1);
                    }
            }
        }
        if ((jt == 2 * qt && wm < 64) || (jt == 2 * qt + 1 && wm >= 64)) {
            const int rg0 = qt * 128 + wm + rowq;
            const int cg0 = jt * 64 + g * 32 + colq;
#pragma unroll
            for (int mt = 0; mt < 2; mt++)
#pragma unroll
                for (int nt = 0; nt < 4; nt++)
#pragma unroll
                    for (int e = 0; e < 4; e++)
                        if (cg0 + nt * 8 + (e & 1) > rg0 + mt * 16 + (e >> 1) * 8)
                            s[mt][nt][e] = -1e30f;
        }
        float psc[2][2];
#pragma unroll
        for (int mt = 0; mt < 2; mt++)
#pragma unroll
            for (int rg = 0; rg < 2; rg++) {
                float tm = -1e30f;
#pragma unroll
                for (int nt = 0; nt < 4; nt++)
                    tm = fmaxf(tm, fmaxf(s[mt][nt][rg*2], s[mt][nt][rg*2+1]));
                tm = fmaxf(tm, __shfl_xor_sync(0xffffffffu, tm, 1));
                tm = fmaxf(tm, __shfl_xor_sync(0xffffffffu, tm, 2));
                float mn = fmaxf(mr[mt][rg], tm);
                float sc = __expf(mr[mt][rg] - mn);
                float rs = 0.0f;
#pragma unroll
                for (int nt = 0; nt < 4; nt++) {
                    float p0 = __expf(s[mt][nt][rg*2] - mn);
                    float p1 = __expf(s[mt][nt][rg*2+1] - mn);
                    s[mt][nt][rg*2] = p0; s[mt][nt][rg*2+1] = p1;
                    rs += p0 + p1;
                }
                rs += __shfl_xor_sync(0xffffffffu, rs, 1);
                rs += __shfl_xor_sync(0xffffffffu, rs, 2);
                lr[mt][rg] = lr[mt][rg] * sc + rs;
                mr[mt][rg] = mn;
                psc[mt][rg] = sc;
            }
#pragma unroll
        for (int mt = 0; mt < 2; mt++)
#pragma unroll
            for (int ot = 0; ot < 8; ot++) {
                O[mt][ot][0] *= psc[mt][0]; O[mt][ot][1] *= psc[mt][0];
                O[mt][ot][2] *= psc[mt][1]; O[mt][ot][3] *= psc[mt][1];
            }
        uint32_t hiA[2][2][4], loA[2][2][4];
#pragma unroll
        for (int mt = 0; mt < 2; mt++)
#pragma unroll
            for (int j2 = 0; j2 < 2; j2++) {
                const float* s0 = s[mt][2*j2];
                const float* s1 = s[mt][2*j2+1];
                hiA[mt][j2][0] = bfpair(s0[0], s0[1]);
                hiA[mt][j2][1] = bfpair(s0[2], s0[3]);
                hiA[mt][j2][2] = bfpair(s1[0], s1[1]);
                hiA[mt][j2][3] = bfpair(s1[2], s1[3]);
                loA[mt][j2][0] = bfpair(bflo(s0[0]), bflo(s0[1]));
                loA[mt][j2][1] = bfpair(bflo(s0[2]), bflo(s0[3]));
                loA[mt][j2][2] = bfpair(bflo(s1[0]), bflo(s1[1]));
                loA[mt][j2][3] = bfpair(bflo(s1[2]), bflo(s1[3]));
            }
        {
            uint32_t vS = sb + FKV + buf * 32768 + 16384;
            const int rV = lane & 15;
#pragma unroll
            for (int jj = 0; jj < 2; jj++) {
                const int grh = 8 * g + 2 * jj + kgl;
                const int grl = grh + 4;
                uint32_t bh4[4][4], bl4[4][4];
#pragma unroll
                for (int ng = 0; ng < 4; ng++) ldsm4(vS + off256(rV + 16*ng, grh), bh4[ng]);
#pragma unroll
                for (int mt = 0; mt < 2; mt++)
#pragma unroll
                    for (int ng = 0; ng < 4; ng++) {
                        uint32_t p0[2] = {bh4[ng][0], bh4[ng][2]};
                        uint32_t p1[2] = {bh4[ng][1], bh4[ng][3]};
                        mma16816(O[mt][ng*2+0], hiA[mt][jj], p0);
                        mma16816(O[mt][ng*2+1], hiA[mt][jj], p1);
                    }
#pragma unroll
                for (int ng = 0; ng < 4; ng++) ldsm4(vS + off256(rV + 16*ng, grl), bl4[ng]);
#pragma unroll
                for (int mt = 0; mt < 2; mt++)
#pragma unroll
                    for (int ng = 0; ng < 4; ng++) {
                        uint32_t p0[2] = {bl4[ng][0], bl4[ng][2]};
                        uint32_t p1[2] = {bl4[ng][1], bl4[ng][3]};
                        mma16816(O[mt][ng*2+0], hiA[mt][jj], p0);
                        mma16816(O[mt][ng*2+1], hiA[mt][jj], p1);
                    }
#pragma unroll
                for (int mt = 0; mt < 2; mt++)
#pragma unroll
                    for (int ng = 0; ng < 4; ng++) {
                        uint32_t p0[2] = {bh4[ng][0], bh4[ng][2]};
                        uint32_t p1[2] = {bh4[ng][1], bh4[ng][3]};
                        mma16816(O[mt][ng*2+0], loA[mt][jj], p0);
                        mma16816(O[mt][ng*2+1], loA[mt][jj], p1);
                    }
            }
        }
    }
    __syncthreads();
    if (g == 1) {
#pragma unroll
        for (int mt = 0; mt < 2; mt++)
#pragma unroll
            for (int rg = 0; rg < 2; rg++) {
                int r = wm + mt * 16 + rowq + rg * 8;
                if ((lane & 3) == 0)
                    *reinterpret_cast<float2*>(sm + FML + r * 8) = make_float2(mr[mt][rg], lr[mt][rg]);
#pragma unroll
                for (int nt = 0; nt < 8; nt++) {
                    int c = nt * 8 + colq;
                    *reinterpret_cast<float2*>(sm + FPS2 + (r * 64 + c) * 4) =
                        make_float2(O[mt][nt][rg*2], O[mt][nt][rg*2+1]);
                }
            }
    }
    __syncthreads();
    if (g == 0) {
        const int h = bh & 15, bb = bh >> 4;
#pragma unroll
        for (int mt = 0; mt < 2; mt++)
#pragma unroll
            for (int rg = 0; rg < 2; rg++) {
                int rl = wm + mt * 16 + rowq + rg * 8;
                float2 ml1 = *reinterpret_cast<float2*>(sm + FML + rl * 8);
                float M = fmaxf(mr[mt][rg], ml1.x);
                float sc0 = __expf(mr[mt][rg] - M), sc1 = __expf(ml1.x - M);
                float inv = 1.0f / (lr[mt][rg] * sc0 + ml1.y * sc1);
                int t = qt * 128 + rl;
                uint32_t* dst = reinterpret_cast<uint32_t*>(
                    g_ap + ((size_t)bb * T_ + t) * KD);
#pragma unroll
                for (int nt = 0; nt < 8; nt++) {
                    int c = nt * 8 + colq;
                    float2 o1 = *reinterpret_cast<float2*>(sm + FPS2 + (rl * 64 + c) * 4);
                    float v0 = (O[mt][nt][rg*2] * sc0 + o1.x * sc1) * inv;
                    float v1 = (O[mt][nt][rg*2+1] * sc0 + o1.y * sc1) * inv;
                    dst[(h * 64 + c) >> 1] = bfpair(v0, v1);
                    dst[(1024 + h * 64 + c) >> 1] = bfpair(bflo(v0), bflo(v1));
                }
            }
    }
}

// ---------------- launch ----------------
extern "C" void kernel_launch(void* const* d_in, const int* in_sizes, int n_in,
                              void* d_out, int out_size)
{
    const float* x  = (const float*)d_in[0];
    const float* Wk = (const float*)d_in[1];
    const float* bk = (const float*)d_in[2];
    const float* Wq = (const float*)d_in[3];
    const float* bq = (const float*)d_in[4];
    const float* Wv = (const float*)d_in[5];
    const float* bv = (const float*)d_in[6];
    const float* Wp = (const float*)d_in[7];
    const float* bp = (const float*)d_in[8];
    float* out = (float*)d_out;

    pack_a_kernel<<<(BT_ * D_) / (4 * 256), 256>>>(x);
    pack_w_kernel<<<dim3(32, 32, 4), 256>>>(Wq, Wk, Wv, Wp);

    cudaFuncSetAttribute(qkv_gemm, cudaFuncAttributeMaxDynamicSharedMemorySize, DSMEM);
    cudaFuncSetAttribute(proj_gemm, cudaFuncAttributeMaxDynamicSharedMemorySize, DSMEM);
    cudaFuncSetAttribute(flash_mma, cudaFuncAttributeMaxDynamicSharedMemorySize, FLASH_SMEM);

    qkv_gemm<<<dim3(8, 64, 3), 256, DSMEM>>>(bq, bk, bv);
    flash_mma<<<dim3(T_ / 128, B_ * NH_), 256, FLASH_SMEM>>>();
    proj_gemm<<<dim3(8, 64), 256, DSMEM>>>(bp, out);
}

// round 10
// speedup vs baseline: 1.8208x; 1.0041x over previous
#include <cuda_runtime.h>
#include <cuda_bf16.h>
#include <cstdint>
#include <math.h>

#define B_  4
#define T_  2048
#define D_  1024
#define NH_ 16
#define HD_ 64
#define BT_ (B_*T_)
#define KD  2048     // dedup GEMM contraction: [h(1024)|l(1024)]
#define KPH 128      // flash packed head dim: [h(64)|l(64)]

__device__ __align__(128) __nv_bfloat16 g_xp[(size_t)BT_*KD];
__device__ __align__(128) __nv_bfloat16 g_wp[4][(size_t)D_*KD];
__device__ __align__(128) __nv_bfloat16 g_ap[(size_t)BT_*KD];
__device__ __align__(128) __nv_bfloat16 g_qp[(size_t)B_*NH_*T_*KPH];
__device__ __align__(128) __nv_bfloat16 g_kp[(size_t)B_*NH_*T_*KPH];
__device__ __align__(128) __nv_bfloat16 g_vp[(size_t)B_*NH_*HD_*2*T_];

__device__ __forceinline__ uint32_t smem_u32(const void* p) {
    uint32_t a;
    asm("{ .reg .u64 t; cvta.to.shared.u64 t, %1; cvt.u32.u64 %0, t; }" : "=r"(a) : "l"(p));
    return a;
}
__device__ __forceinline__ void cp_async16(uint32_t s, const void* g) {
    asm volatile("cp.async.cg.shared.global [%0], [%1], 16;" :: "r"(s), "l"(g));
}
#define CP_COMMIT() asm volatile("cp.async.commit_group;" ::: "memory")
#define CP_WAIT1()  asm volatile("cp.async.wait_group 1;" ::: "memory")
#define CP_WAIT0()  asm volatile("cp.async.wait_group 0;" ::: "memory")
__device__ __forceinline__ void ldsm4(uint32_t addr, uint32_t r[4]) {
    asm volatile("ldmatrix.sync.aligned.m8n8.x4.shared.b16 {%0,%1,%2,%3}, [%4];"
                 : "=r"(r[0]), "=r"(r[1]), "=r"(r[2]), "=r"(r[3]) : "r"(addr));
}
__device__ __forceinline__ void mma16816(float d[4], const uint32_t a[4], const uint32_t b[2]) {
    asm volatile("mma.sync.aligned.m16n8k16.row.col.f32.bf16.bf16.f32 "
                 "{%0,%1,%2,%3}, {%4,%5,%6,%7}, {%8,%9}, {%0,%1,%2,%3};"
                 : "+f"(d[0]), "+f"(d[1]), "+f"(d[2]), "+f"(d[3])
                 : "r"(a[0]), "r"(a[1]), "r"(a[2]), "r"(a[3]), "r"(b[0]), "r"(b[1]));
}
__device__ __forceinline__ uint32_t bfpair(float x, float y) {
    __nv_bfloat162 t = __floats2bfloat162_rn(x, y);
    return *reinterpret_cast<uint32_t*>(&t);
}
__device__ __forceinline__ float bflo(float x) {
    return x - __bfloat162float(__float2bfloat16(x));
}

// ---------------- pack kernels (dedup [h|l]) ----------------
__global__ __launch_bounds__(256) void pack_a_kernel(const float* __restrict__ X)
{
    int idx = blockIdx.x * 256 + threadIdx.x;
    size_t e = (size_t)idx * 4;
    float4 v = reinterpret_cast<const float4*>(X)[idx];
    int m = (int)(e >> 10), k = (int)(e & 1023);
    uint32_t* dst = reinterpret_cast<uint32_t*>(g_xp + (size_t)m * KD);
    dst[(k >> 1) + 0] = bfpair(v.x, v.y);
    dst[(k >> 1) + 1] = bfpair(v.z, v.w);
    dst[((1024 + k) >> 1) + 0] = bfpair(bflo(v.x), bflo(v.y));
    dst[((1024 + k) >> 1) + 1] = bfpair(bflo(v.z), bflo(v.w));
}

__global__ __launch_bounds__(256) void pack_w_kernel(
    const float* __restrict__ Wq, const float* __restrict__ Wk,
    const float* __restrict__ Wv, const float* __restrict__ Wp)
{
    const float* W = (blockIdx.z == 0) ? Wq : (blockIdx.z == 1) ? Wk :
                     (blockIdx.z == 2) ? Wv : Wp;
    __nv_bfloat16* out = g_wp[blockIdx.z];
    __shared__ float tile[32][33];
    const int tid = threadIdx.x;
    const int n0 = blockIdx.x * 32, k0 = blockIdx.y * 32;
#pragma unroll
    for (int i = 0; i < 4; i++) {
        int kk = (tid >> 5) + i * 8;
        tile[kk][tid & 31] = W[(size_t)(k0 + kk) * D_ + n0 + (tid & 31)];
    }
    __syncthreads();
#pragma unroll
    for (int i = 0; i < 4; i++) {
        int nn = (tid >> 5) + i * 8, kl = tid & 31;
        float v = tile[kl][nn];
        __nv_bfloat16 hi = __float2bfloat16(v);
        size_t base = (size_t)(n0 + nn) * KD + (k0 + kl);
        out[base] = hi;
        out[base + 1024] = __float2bfloat16(v - __bfloat162float(hi));
    }
}

// ---------------- dedup HMMA GEMM (128x128, 32 real k per iter, 3 stages) ----------------
#define DSTAGE 32768
#define DSMEM (3 * DSTAGE)
#define DNIT (D_ / 32)     // 32

__device__ __forceinline__ uint32_t sw_off(int r, int g) {
    return (uint32_t)(r * 64 + ((g ^ ((r >> 1) & 3)) << 4));
}
__device__ __forceinline__ void load_stage2(uint32_t sbuf,
                                            const __nv_bfloat16* __restrict__ A,
                                            const __nv_bfloat16* __restrict__ B, int k)
{
    const int tid = threadIdx.x;
#pragma unroll
    for (int i = 0; i < 8; i++) {
        int ch = tid + i * 256;          // 0..2047
        int reg = ch >> 9;               // 0=Ah 1=Al 2=Bh 3=Bl
        int r = (ch & 511) >> 2, gc = ch & 3;
        const __nv_bfloat16* base = (reg & 2) ? B : A;
        int off = (reg & 1) ? 1024 : 0;
        cp_async16(sbuf + reg * 8192 + sw_off(r, gc),
                   base + (size_t)r * KD + off + k + gc * 8);
    }
}
__device__ __forceinline__ void mma_blk(float acc[2][8][4], const uint32_t a[2][4],
                                        const uint32_t bp[2][4], int off) {
#pragma unroll
    for (int mt = 0; mt < 2; mt++)
#pragma unroll
        for (int kk = 0; kk < 2; kk++) {
            uint32_t q0[2] = {bp[kk][0], bp[kk][2]};
            uint32_t q1[2] = {bp[kk][1], bp[kk][3]};
            mma16816(acc[mt][off + kk*2 + 0], a[mt], q0);
            mma16816(acc[mt][off + kk*2 + 1], a[mt], q1);
        }
}
__device__ __forceinline__ void gemm_main2(uint32_t smem,
                                           const __nv_bfloat16* __restrict__ A,
                                           const __nv_bfloat16* __restrict__ B,
                                           float acc[2][8][4])
{
    const int tid = threadIdx.x, lane = tid & 31, wid = tid >> 5;
    const int wm = (wid & 3) * 32, wn = (wid >> 2) * 64;
    for (int s = 0; s < 2; s++) { load_stage2(smem + s * DSTAGE, A, B, s * 32); CP_COMMIT(); }
    const int rA = wm + (lane & 15), rB = wn + (lane & 15), kgl = (lane >> 4) & 1;
    int st3 = 0, ld3 = 2;
    for (int ks = 0; ks < DNIT; ks++) {
        CP_WAIT1();
        __syncthreads();
        if (ks + 2 < DNIT) load_stage2(smem + ld3 * DSTAGE, A, B, (ks + 2) * 32);
        CP_COMMIT();
        uint32_t stb = smem + st3 * DSTAGE;
#pragma unroll
        for (int kh = 0; kh < 2; kh++) {
            const int kg = kh * 2 + kgl;
            uint32_t aH[2][4], aL[2][4], bx[2][4], by[2][4];
            ldsm4(stb + sw_off(rA, kg), aH[0]);
            ldsm4(stb + sw_off(rA + 16, kg), aH[1]);
            ldsm4(stb + 16384 + sw_off(rB, kg), bx[0]);
            ldsm4(stb + 16384 + sw_off(rB + 16, kg), bx[1]);
            mma_blk(acc, aH, bx, 0);
            ldsm4(stb + 16384 + sw_off(rB + 32, kg), by[0]);
            ldsm4(stb + 16384 + sw_off(rB + 48, kg), by[1]);
            mma_blk(acc, aH, by, 4);
            ldsm4(stb + 8192 + sw_off(rA, kg), aL[0]);
            ldsm4(stb + 8192 + sw_off(rA + 16, kg), aL[1]);
            mma_blk(acc, aL, bx, 0);
            mma_blk(acc, aL, by, 4);
            ldsm4(stb + 24576 + sw_off(rB, kg), bx[0]);
            ldsm4(stb + 24576 + sw_off(rB + 16, kg), bx[1]);
            mma_blk(acc, aH, bx, 0);
            ldsm4(stb + 24576 + sw_off(rB + 32, kg), by[0]);
            ldsm4(stb + 24576 + sw_off(rB + 48, kg), by[1]);
            mma_blk(acc, aH, by, 4);
        }
        st3 = (st3 == 2) ? 0 : st3 + 1;
        ld3 = (ld3 == 2) ? 0 : ld3 + 1;
    }
}

__global__ __launch_bounds__(256, 2) void qkv_gemm(
    const float* __restrict__ bq, const float* __restrict__ bk, const float* __restrict__ bv)
{
    extern __shared__ __align__(128) char smem[];
    uint32_t sb = smem_u32(smem);
    const int z = blockIdx.z;
    const int m0 = blockIdx.y * 128, n0 = blockIdx.x * 128;
    float acc[2][8][4] = {};
    gemm_main2(sb, g_xp + (size_t)m0 * KD, g_wp[z] + (size_t)n0 * KD, acc);

    const float* bias = (z == 0) ? bq : (z == 1) ? bk : bv;
    const int lane = threadIdx.x & 31, wid = threadIdx.x >> 5;
    const int wm = (wid & 3) * 32, wn = (wid >> 2) * 64;
    const int row_l = lane >> 2, col_l = (lane & 3) * 2;

    if (z <= 1) {
        const int h = (n0 + wn) >> 6;
        __nv_bfloat16* dstp = (z == 0) ? g_qp : g_kp;
#pragma unroll
        for (int mt = 0; mt < 2; mt++) {
            int mr = m0 + wm + mt * 16 + row_l;
            int bb = mr >> 11, t = mr & (T_ - 1);
            uint32_t* r0p = reinterpret_cast<uint32_t*>(dstp + ((size_t)(bb*NH_+h)*T_ + t) * KPH);
            uint32_t* r8p = r0p + 8 * (KPH / 2);
#pragma unroll
            for (int nt = 0; nt < 8; nt++) {
                int c = nt * 8 + col_l;
                float bxs = bias[n0+wn+c], bys = bias[n0+wn+c+1];
                float v0x = acc[mt][nt][0]+bxs, v0y = acc[mt][nt][1]+bys;
                float v1x = acc[mt][nt][2]+bxs, v1y = acc[mt][nt][3]+bys;
                int ci = nt * 4 + (lane & 3);
                r0p[ci] = bfpair(v0x, v0y); r0p[32+ci] = bfpair(bflo(v0x), bflo(v0y));
                r8p[ci] = bfpair(v1x, v1y); r8p[32+ci] = bfpair(bflo(v1x), bflo(v1y));
            }
        }
    } else {
        // fused V transpose-pack via (dead) stage smem
        float* vt = reinterpret_cast<float*>(smem);
        __syncthreads();
#pragma unroll
        for (int mt = 0; mt < 2; mt++) {
            int rl = wm + mt * 16 + row_l;
#pragma unroll
            for (int nt = 0; nt < 8; nt++) {
                int cl = wn + nt * 8 + col_l;
                float bxs = bias[n0+cl], bys = bias[n0+cl+1];
                vt[rl * 130 + cl]           = acc[mt][nt][0] + bxs;
                vt[rl * 130 + cl + 1]       = acc[mt][nt][1] + bys;
                vt[(rl + 8) * 130 + cl]     = acc[mt][nt][2] + bxs;
                vt[(rl + 8) * 130 + cl + 1] = acc[mt][nt][3] + bys;
            }
        }
        __syncthreads();
        const int tid = threadIdx.x;
        const int c_loc = tid >> 1, half = tid & 1;
        const int h = (n0 + c_loc) >> 6;
        const int c = c_loc & 63;
        const int bb = m0 >> 11, t0 = m0 & (T_ - 1);
        const int bh = bb * NH_ + h;
        const int tl = (t0 >> 6) + half;
        uint32_t outbuf[64];
#pragma unroll
        for (int grp = 0; grp < 2; grp++)
#pragma unroll
            for (int sl2 = 0; sl2 < 16; sl2++) {
                float v0 = vt[(half*64 + grp*32 + 2*sl2)     * 130 + c_loc];
                float v1 = vt[(half*64 + grp*32 + 2*sl2 + 1) * 130 + c_loc];
                outbuf[grp*32 + sl2]      = bfpair(v0, v1);
                outbuf[grp*32 + 16 + sl2] = bfpair(bflo(v0), bflo(v1));
            }
        uint4* dst = reinterpret_cast<uint4*>(
            g_vp + (size_t)bh * HD_ * 2 * T_ + (size_t)c * 2 * T_ + tl * 128);
#pragma unroll
        for (int q = 0; q < 16; q++) dst[q] = reinterpret_cast<uint4*>(outbuf)[q];
    }
}

__global__ __launch_bounds__(256, 2) void proj_gemm(const float* __restrict__ bp, float* __restrict__ outC)
{
    extern __shared__ __align__(128) char smem[];
    uint32_t sb = smem_u32(smem);
    const int m0 = blockIdx.y * 128, n0 = blockIdx.x * 128;
    float acc[2][8][4] = {};
    gemm_main2(sb, g_ap + (size_t)m0 * KD, g_wp[3] + (size_t)n0 * KD, acc);
    const int lane = threadIdx.x & 31, wid = threadIdx.x >> 5;
    const int wm = (wid & 3) * 32, wn = (wid >> 2) * 64;
    const int row_l = lane >> 2, col_l = (lane & 3) * 2;
#pragma unroll
    for (int mt = 0; mt < 2; mt++) {
        int m = m0 + wm + mt * 16 + row_l;
        float* r0p = outC + (size_t)m * D_;
        float* r8p = r0p + 8 * D_;
#pragma unroll
        for (int nt = 0; nt < 8; nt++) {
            int n = n0 + wn + nt * 8 + col_l;
            float2 bi = *reinterpret_cast<const float2*>(&bp[n]);
            float2 v0 = {acc[mt][nt][0]+bi.x, acc[mt][nt][1]+bi.y};
            float2 v1 = {acc[mt][nt][2]+bi.x, acc[mt][nt][3]+bi.y};
            *reinterpret_cast<float2*>(r0p + n) = v0;
            *reinterpret_cast<float2*>(r8p + n) = v1;
        }
    }
}

// ---------------- HMMA flash: 512 threads, 16 warps (8M x 2KV), 16x32 warp tile ----------------
#define FQS 0
#define FKV 32768
#define FPS2 32768
#define FML 65536
#define FLASH_SMEM 98304
#define FTHREADS 512

__device__ __forceinline__ uint32_t off256(int r, int g) {
    return (uint32_t)(r * 256 + ((g ^ (r & 7)) << 4));
}
__device__ __forceinline__ void f_kv(uint32_t sb, const char* gk, const char* gv, int jt, int buf)
{
    const int tid = threadIdx.x;
    uint32_t ks = sb + FKV + buf * 32768;
    uint32_t vs = ks + 16384;
#pragma unroll
    for (int i = 0; i < 2; i++) {
        int ch = tid + i * FTHREADS;      // 0..1023
        int r = ch >> 4, gr = ch & 15;
        cp_async16(ks + off256(r, gr), gk + ((size_t)(jt*64 + r)*KPH + gr*8) * 2);
    }
#pragma unroll
    for (int i = 0; i < 2; i++) {
        int ch = tid + i * FTHREADS;
        int r = ch >> 4, gr = ch & 15;
        cp_async16(vs + off256(r, gr), gv + ((size_t)r*2*T_ + jt*128 + gr*8) * 2);
    }
}

__global__ void __launch_bounds__(FTHREADS, 1) flash_mma()
{
    extern __shared__ __align__(128) char sm[];
    uint32_t sb = smem_u32(sm);
    const int qt = (T_/128 - 1) - blockIdx.x;
    const int bh = blockIdx.y;
    const int tid = threadIdx.x, lane = tid & 31, w = tid >> 5;
    const int wm = (w & 7) * 16;          // M position (16 rows)
    const int g = w >> 3;                 // key half
    const int rowq = lane >> 2, colq = (lane & 3) * 2;
    const int rA = wm + (lane & 15), kgl = (lane >> 4) & 1;

    const char* gq = (const char*)(g_qp + ((size_t)bh*T_ + (size_t)qt*128) * KPH);
    const char* gk = (const char*)(g_kp + (size_t)bh*T_*KPH);
    const char* gv = (const char*)(g_vp + (size_t)bh*HD_*2*T_);

#pragma unroll
    for (int i = 0; i < 4; i++) {
        int ch = tid + i * FTHREADS;      // 0..2047
        int r = ch >> 4, gr = ch & 15;
        cp_async16(sb + FQS + off256(r, gr), gq + ((size_t)r*KPH + gr*8) * 2);
    }
    f_kv(sb, gk, gv, 0, 0);
    CP_COMMIT();

    float O[8][4] = {};
    float mr[2] = {-1e30f, -1e30f};
    float lr[2] = {0.f, 0.f};

    const int njt = 2 * qt + 2;
    for (int jt = 0; jt < njt; jt++) {
        const int buf = jt & 1;
        CP_WAIT0();
        __syncthreads();
        if (jt + 1 < njt) { f_kv(sb, gk, gv, jt + 1, buf ^ 1); CP_COMMIT(); }

        // exact per-warp-tile causal classification
        const int dk = (jt - 2 * qt) * 64 + g * 32;   // tile key start relative to row block
        const bool in_diag = (jt >= 2 * qt);
        if (in_diag && dk > wm + 15) continue;        // fully masked

        // ---- S = QK^T (16 rows x 32 keys), 3-term ----
        float s[4][4] = {};
        {
            uint32_t kS = sb + FKV + buf * 32768;
            const int rB = g * 32 + (lane & 15);
#pragma unroll
            for (int j = 0; j < 4; j++) {
                const int grh = 2 * j + kgl, grl = 8 + 2 * j + kgl;
                uint32_t aH[4], aL[4], bH[2][4], bL[2][4];
                ldsm4(sb + FQS + off256(rA, grh), aH);
                ldsm4(kS + off256(rB, grh), bH[0]);
                ldsm4(kS + off256(rB + 16, grh), bH[1]);
#pragma unroll
                for (int kk = 0; kk < 2; kk++) {
                    uint32_t p0[2] = {bH[kk][0], bH[kk][2]};
                    uint32_t p1[2] = {bH[kk][1], bH[kk][3]};
                    mma16816(s[kk*2+0], aH, p0);
                    mma16816(s[kk*2+1], aH, p1);
                }
                ldsm4(sb + FQS + off256(rA, grl), aL);
#pragma unroll
                for (int kk = 0; kk < 2; kk++) {
                    uint32_t p0[2] = {bH[kk][0], bH[kk][2]};
                    uint32_t p1[2] = {bH[kk][1], bH[kk][3]};
                    mma16816(s[kk*2+0], aL, p0);
                    mma16816(s[kk*2+1], aL, p1);
                }
                ldsm4(kS + off256(rB, grl), bL[0]);
                ldsm4(kS + off256(rB + 16, grl), bL[1]);
#pragma unroll
                for (int kk = 0; kk < 2; kk++) {
                    uint32_t p0[2] = {bL[kk][0], bL[kk][2]};
                    uint32_t p1[2] = {bL[kk][1], bL[kk][3]};
                    mma16816(s[kk*2+0], aH, p0);
                    mma16816(s[kk*2+1], aH, p1);
                }
            }
        }
        // mask only when the diagonal crosses this 16x32 tile
        if (in_diag && dk + 31 > wm) {
            const int rg0 = wm + rowq;
            const int cg0 = dk + colq;
#pragma unroll
            for (int nt = 0; nt < 4; nt++)
#pragma unroll
                for (int e = 0; e < 4; e++)
                    if (cg0 + nt * 8 + (e & 1) > rg0 + (e >> 1) * 8)
                        s[nt][e] = -1e30f;
        }
        // ---- online softmax (per 8-row group) ----
        float psc[2];
#pragma unroll
        for (int rg = 0; rg < 2; rg++) {
            float tm = -1e30f;
#pragma unroll
            for (int nt = 0; nt < 4; nt++)
                tm = fmaxf(tm, fmaxf(s[nt][rg*2], s[nt][rg*2+1]));
            tm = fmaxf(tm, __shfl_xor_sync(0xffffffffu, tm, 1));
            tm = fmaxf(tm, __shfl_xor_sync(0xffffffffu, tm, 2));
            float mn = fmaxf(mr[rg], tm);
            float sc = __expf(mr[rg] - mn);
            float rs = 0.0f;
#pragma unroll
            for (int nt = 0; nt < 4; nt++) {
                float p0 = __expf(s[nt][rg*2] - mn);
                float p1 = __expf(s[nt][rg*2+1] - mn);
                s[nt][rg*2] = p0; s[nt][rg*2+1] = p1;
                rs += p0 + p1;
            }
            rs += __shfl_xor_sync(0xffffffffu, rs, 1);
            rs += __shfl_xor_sync(0xffffffffu, rs, 2);
            lr[rg] = lr[rg] * sc + rs;
            mr[rg] = mn;
            psc[rg] = sc;
        }
#pragma unroll
        for (int ot = 0; ot < 8; ot++) {
            O[ot][0] *= psc[0]; O[ot][1] *= psc[0];
            O[ot][2] *= psc[1]; O[ot][3] *= psc[1];
        }
        // ---- P fragments in registers ----
        uint32_t hiA[2][4], loA[2][4];
#pragma unroll
        for (int j2 = 0; j2 < 2; j2++) {
            const float* s0 = s[2*j2];
            const float* s1 = s[2*j2+1];
            hiA[j2][0] = bfpair(s0[0], s0[1]);
            hiA[j2][1] = bfpair(s0[2], s0[3]);
            hiA[j2][2] = bfpair(s1[0], s1[1]);
            hiA[j2][3] = bfpair(s1[2], s1[3]);
            loA[j2][0] = bfpair(bflo(s0[0]), bflo(s0[1]));
            loA[j2][1] = bfpair(bflo(s0[2]), bflo(s0[3]));
            loA[j2][2] = bfpair(bflo(s1[0]), bflo(s1[1]));
            loA[j2][3] = bfpair(bflo(s1[2]), bflo(s1[3]));
        }
        // ---- O += P·V (3-term) ----
        {
            uint32_t vS = sb + FKV + buf * 32768 + 16384;
            const int rV = lane & 15;
#pragma unroll
            for (int jj = 0; jj < 2; jj++) {
                const int grh = 8 * g + 2 * jj + kgl;
                const int grl = grh + 4;
                uint32_t bh4[4][4], bl4[4][4];
#pragma unroll
                for (int ng = 0; ng < 4; ng++) ldsm4(vS + off256(rV + 16*ng, grh), bh4[ng]);
#pragma unroll
                for (int ng = 0; ng < 4; ng++) {
                    uint32_t p0[2] = {bh4[ng][0], bh4[ng][2]};
                    uint32_t p1[2] = {bh4[ng][1], bh4[ng][3]};
                    mma16816(O[ng*2+0], hiA[jj], p0);
                    mma16816(O[ng*2+1], hiA[jj], p1);
                }
#pragma unroll
                for (int ng = 0; ng < 4; ng++) ldsm4(vS + off256(rV + 16*ng, grl), bl4[ng]);
#pragma unroll
                for (int ng = 0; ng < 4; ng++) {
                    uint32_t p0[2] = {bl4[ng][0], bl4[ng][2]};
                    uint32_t p1[2] = {bl4[ng][1], bl4[ng][3]};
                    mma16816(O[ng*2+0], hiA[jj], p0);
                    mma16816(O[ng*2+1], hiA[jj], p1);
                }
#pragma unroll
                for (int ng = 0; ng < 4; ng++) {
                    uint32_t p0[2] = {bh4[ng][0], bh4[ng][2]};
                    uint32_t p1[2] = {bh4[ng][1], bh4[ng][3]};
                    mma16816(O[ng*2+0], loA[jj], p0);
                    mma16816(O[ng*2+1], loA[jj], p1);
                }
            }
        }
    }
    // ---- merge halves (reuses dead KV smem) ----
    __syncthreads();
    if (g == 1) {
#pragma unroll
        for (int rg = 0; rg < 2; rg++) {
            int r = wm + rowq + rg * 8;
            if ((lane & 3) == 0)
                *reinterpret_cast<float2*>(sm + FML + r * 8) = make_float2(mr[rg], lr[rg]);
#pragma unroll
            for (int nt = 0; nt < 8; nt++) {
                int c = nt * 8 + colq;
                *reinterpret_cast<float2*>(sm + FPS2 + (r * 64 + c) * 4) =
                    make_float2(O[nt][rg*2], O[nt][rg*2+1]);
            }
        }
    }
    __syncthreads();
    if (g == 0) {
        const int h = bh & 15, bb = bh >> 4;
#pragma unroll
        for (int rg = 0; rg < 2; rg++) {
            int rl = wm + rowq + rg * 8;
            float2 ml1 = *reinterpret_cast<float2*>(sm + FML + rl * 8);
            float M = fmaxf(mr[rg], ml1.x);
            float sc0 = __expf(mr[rg] - M), sc1 = __expf(ml1.x - M);
            float inv = 1.0f / (lr[rg] * sc0 + ml1.y * sc1);
            int t = qt * 128 + rl;
            uint32_t* dst = reinterpret_cast<uint32_t*>(g_ap + ((size_t)bb * T_ + t) * KD);
#pragma unroll
            for (int nt = 0; nt < 8; nt++) {
                int c = nt * 8 + colq;
                float2 o1 = *reinterpret_cast<float2*>(sm + FPS2 + (rl * 64 + c) * 4);
                float v0 = (O[nt][rg*2] * sc0 + o1.x * sc1) * inv;
                float v1 = (O[nt][rg*2+1] * sc0 + o1.y * sc1) * inv;
                dst[(h * 64 + c) >> 1] = bfpair(v0, v1);
                dst[(1024 + h * 64 + c) >> 1] = bfpair(bflo(v0), bflo(v1));
            }
        }
    }
}

// ---------------- launch ----------------
extern "C" void kernel_launch(void* const* d_in, const int* in_sizes, int n_in,
                              void* d_out, int out_size)
{
    const float* x  = (const float*)d_in[0];
    const float* Wk = (const float*)d_in[1];
    const float* bk = (const float*)d_in[2];
    const float* Wq = (const float*)d_in[3];
    const float* bq = (const float*)d_in[4];
    const float* Wv = (const float*)d_in[5];
    const float* bv = (const float*)d_in[6];
    const float* Wp = (const float*)d_in[7];
    const float* bp = (const float*)d_in[8];
    float* out = (float*)d_out;

    pack_a_kernel<<<(BT_ * D_) / (4 * 256), 256>>>(x);
    pack_w_kernel<<<dim3(32, 32, 4), 256>>>(Wq, Wk, Wv, Wp);

    cudaFuncSetAttribute(qkv_gemm, cudaFuncAttributeMaxDynamicSharedMemorySize, DSMEM);
    cudaFuncSetAttribute(proj_gemm, cudaFuncAttributeMaxDynamicSharedMemorySize, DSMEM);
    cudaFuncSetAttribute(flash_mma, cudaFuncAttributeMaxDynamicSharedMemorySize, FLASH_SMEM);

    qkv_gemm<<<dim3(8, 64, 3), 256, DSMEM>>>(bq, bk, bv);
    flash_mma<<<dim3(T_ / 128, B_ * NH_), FTHREADS, FLASH_SMEM>>>();
    proj_gemm<<<dim3(8, 64), 256, DSMEM>>>(bp, out);
}